// round 8
// baseline (speedup 1.0000x reference)
#include <cuda_runtime.h>
#include <cuda_bf16.h>
#include <math.h>
#include <stdint.h>

#define NN 50000
#define NE 800000
#define MPAD 50048   // 391 * 128

// ---------------- device scratch (allocation-free) ----------------
__device__ float g_buf1[NN * 512];          // GEMM f32 output
__device__ float g_buf2[NN * 512];          // heads temp
__device__ __nv_bfloat16 g_A2[(size_t)MPAD * 1024];   // [Ah | Al] bf16, K-contig rows
__device__ __nv_bfloat16 g_Bt1[512 * 1024];           // [Bh | Bl], N-major rows, K-contig
__device__ __nv_bfloat16 g_Bt2[512 * 1024];
__device__ __nv_bfloat16 g_Bt3[256 * 1024];
__device__ float g_dis[NN];
__device__ int   g_indeg[NN];
__device__ int   g_rowptr[NN + 1];
__device__ int   g_cursor[NN];
__device__ int2  g_colval[NE];              // (col, val bits)
__device__ float g_Wall[256 * 72];
__device__ float g_ball[72];
__device__ int   g_blocksum[64];

// ---------------- helpers ----------------
__device__ __forceinline__ uint32_t smem_u32(const void* p) {
    uint32_t a;
    asm("{ .reg .u64 t; cvta.to.shared.u64 t, %1; cvt.u32.u64 %0, t; }" : "=r"(a) : "l"(p));
    return a;
}
__device__ __forceinline__ void ldsm4(uint32_t* r, uint32_t addr) {
    asm volatile("ldmatrix.sync.aligned.m8n8.x4.shared.b16 {%0,%1,%2,%3}, [%4];"
                 : "=r"(r[0]), "=r"(r[1]), "=r"(r[2]), "=r"(r[3]) : "r"(addr));
}
__device__ __forceinline__ void mma16816(float* c, const uint32_t* a, const uint32_t* b) {
    asm volatile("mma.sync.aligned.m16n8k16.row.col.f32.bf16.bf16.f32 "
                 "{%0,%1,%2,%3}, {%4,%5,%6,%7}, {%8,%9}, {%0,%1,%2,%3};"
                 : "+f"(c[0]), "+f"(c[1]), "+f"(c[2]), "+f"(c[3])
                 : "r"(a[0]), "r"(a[1]), "r"(a[2]), "r"(a[3]), "r"(b[0]), "r"(b[1]));
}
#define CP_ASYNC16(dst, src) \
    asm volatile("cp.async.cg.shared.global [%0], [%1], 16;" :: "r"(dst), "l"(src))
#define CP_COMMIT() asm volatile("cp.async.commit_group;" ::: "memory")
#define CP_WAIT2()  asm volatile("cp.async.wait_group 2;" ::: "memory")

// ---------------- CSR build ----------------
__global__ void zero_indeg_kernel() {
    int i = blockIdx.x * blockDim.x + threadIdx.x;
    if (i < NN) g_indeg[i] = 0;
}
__global__ void count_kernel(const int* __restrict__ dst) {
    int e = blockIdx.x * blockDim.x + threadIdx.x;
    if (e < NE) atomicAdd(&g_indeg[dst[e]], 1);
}
__global__ void dis_kernel() {
    int i = blockIdx.x * blockDim.x + threadIdx.x;
    if (i < NN) g_dis[i] = rsqrtf((float)(g_indeg[i] + 1));
}
__global__ void scan_part1() {   // grid 49, block 1024: block sums
    __shared__ int ws[32];
    int i = blockIdx.x * 1024 + threadIdx.x;
    int v = (i < NN) ? g_indeg[i] : 0;
    #pragma unroll
    for (int o = 16; o > 0; o >>= 1) v += __shfl_down_sync(0xffffffffu, v, o);
    if ((threadIdx.x & 31) == 0) ws[threadIdx.x >> 5] = v;
    __syncthreads();
    if (threadIdx.x < 32) {
        int s = ws[threadIdx.x];
        #pragma unroll
        for (int o = 16; o > 0; o >>= 1) s += __shfl_down_sync(0xffffffffu, s, o);
        if (threadIdx.x == 0) g_blocksum[blockIdx.x] = s;
    }
}
__global__ void scan_part2() {   // 1 thread
    int acc = 0;
    for (int b = 0; b < 49; ++b) { int t = g_blocksum[b]; g_blocksum[b] = acc; acc += t; }
    g_rowptr[NN] = acc;
}
__global__ void scan_part3() {   // grid 49, block 1024: local scan + offset
    __shared__ int ws[32];
    int tid = threadIdx.x;
    int i = blockIdx.x * 1024 + tid;
    int v = (i < NN) ? g_indeg[i] : 0;
    int x = v;
    #pragma unroll
    for (int o = 1; o < 32; o <<= 1) {
        int t = __shfl_up_sync(0xffffffffu, x, o);
        if ((tid & 31) >= o) x += t;
    }
    if ((tid & 31) == 31) ws[tid >> 5] = x;
    __syncthreads();
    if (tid < 32) {
        int s = ws[tid];
        #pragma unroll
        for (int o = 1; o < 32; o <<= 1) {
            int t = __shfl_up_sync(0xffffffffu, s, o);
            if (tid >= o) s += t;
        }
        ws[tid] = s;
    }
    __syncthreads();
    int wofs = (tid >= 32) ? ws[(tid >> 5) - 1] : 0;
    int excl = x + wofs - v + g_blocksum[blockIdx.x];
    if (i < NN) { g_rowptr[i] = excl; g_cursor[i] = excl; }
}
__global__ void scatter_kernel(const int* __restrict__ src, const int* __restrict__ dst) {
    int e = blockIdx.x * blockDim.x + threadIdx.x;
    if (e < NE) {
        int s = src[e], d = dst[e];
        int p = atomicAdd(&g_cursor[d], 1);
        g_colval[p] = make_int2(s, __float_as_int(g_dis[s] * g_dis[d]));
    }
}

// ---------------- bf16 split conversions ----------------
__device__ __forceinline__ uint32_t pack_bf2(float a, float b) {
    __nv_bfloat162 h = __floats2bfloat162_rn(a, b);
    return *(uint32_t*)&h;
}
__device__ __forceinline__ void split4(const float4& v, uint2& hi, uint2& lo) {
    __nv_bfloat16 hx = __float2bfloat16_rn(v.x), hy = __float2bfloat16_rn(v.y);
    __nv_bfloat16 hz = __float2bfloat16_rn(v.z), hw = __float2bfloat16_rn(v.w);
    float lx = v.x - __bfloat162float(hx), ly = v.y - __bfloat162float(hy);
    float lz = v.z - __bfloat162float(hz), lw = v.w - __bfloat162float(hw);
    __nv_bfloat162 h01 = __floats2bfloat162_rn(__bfloat162float(hx), __bfloat162float(hy));
    __nv_bfloat162 h23 = __floats2bfloat162_rn(__bfloat162float(hz), __bfloat162float(hw));
    hi.x = *(uint32_t*)&h01; hi.y = *(uint32_t*)&h23;
    lo.x = pack_bf2(lx, ly); lo.y = pack_bf2(lz, lw);
}

__global__ void convert_x_kernel(const float* __restrict__ X) {
    int idx = blockIdx.x * 256 + threadIdx.x;
    if (idx >= MPAD * 128) return;
    int row = idx >> 7, col = (idx & 127) << 2;
    uint2 hi = make_uint2(0, 0), lo = make_uint2(0, 0);
    if (row < NN) {
        float4 v = *(const float4*)(X + (size_t)row * 512 + col);
        split4(v, hi, lo);
    }
    *(uint2*)(g_A2 + (size_t)row * 1024 + col) = hi;
    *(uint2*)(g_A2 + (size_t)row * 1024 + 512 + col) = lo;
}

// W [K=512][N] f32 -> Bt [N][1024] bf16 ([Bh|Bl]), N-major rows
__global__ void convert_B_kernel(const float* __restrict__ W, __nv_bfloat16* __restrict__ Bt, int N) {
    int idx = blockIdx.x * 256 + threadIdx.x;
    if (idx >= 512 * N) return;
    int k = idx / N, n = idx % N;
    float v = W[idx];
    __nv_bfloat16 hi = __float2bfloat16_rn(v);
    float l = v - __bfloat162float(hi);
    Bt[(size_t)n * 1024 + k] = hi;
    Bt[(size_t)n * 1024 + 512 + k] = __float2bfloat16_rn(l);
}

// ---------------- mma.sync GEMM: C[M,N] = A2 @ Bt^T (3-term bf16 split, fp32 accum) ----
// A2: [MPAD,1024] bf16 K-contig. Bt: [N,1024] bf16 K-contig. 48 K-stages of 32.
// CTA 128x128, 8 warps of 64x32. 4-stage cp.async pipeline, dynamic smem.
// Smem rows strided 40 elems (80B) => conflict-free ldmatrix.
#define SROW 40
#define STG_BYTES (128 * SROW * 2)   // 10240 B per tile per stage
__global__ __launch_bounds__(256) void gemm_mma_kernel(
    const __nv_bfloat16* __restrict__ A2, const __nv_bfloat16* __restrict__ Bt,
    float* __restrict__ C, int M, int N)
{
    extern __shared__ __align__(16) __nv_bfloat16 dsmem[];
    const uint32_t as_u32 = smem_u32(dsmem);                  // 4 stages A
    const uint32_t bs_u32 = as_u32 + 4 * STG_BYTES;           // 4 stages B

    const int tid = threadIdx.x;
    const int wid = tid >> 5, lane = tid & 31;
    const int bm = blockIdx.y * 128;
    const int bn = blockIdx.x * 128;
    const int warp_m = (wid >> 2) * 64;   // 0 or 64
    const int warp_n = (wid & 3) * 32;    // 0..96

    const int lrow = tid >> 2;        // 0..63 (x2 via i loop)
    const int lseg = (tid & 3) << 3;  // element offset 0,8,16,24

    auto gload_async = [&](int s) {
        int term = s >> 4, kk = (s & 15) << 5;
        int ac = ((term == 1) ? 512 : 0) + kk;   // A terms: Ah, Al, Ah
        int bc = ((term == 2) ? 512 : 0) + kk;   // B terms: Bh, Bh, Bl
        uint32_t ab = as_u32 + (uint32_t)(s & 3) * STG_BYTES;
        uint32_t bb = bs_u32 + (uint32_t)(s & 3) * STG_BYTES;
        #pragma unroll
        for (int i = 0; i < 2; ++i) {
            int row = lrow + i * 64;
            const __nv_bfloat16* pa = A2 + (size_t)(bm + row) * 1024 + ac + lseg;
            const __nv_bfloat16* pb = Bt + (size_t)(bn + row) * 1024 + bc + lseg;
            uint32_t off = (uint32_t)(row * SROW + lseg) * 2;
            CP_ASYNC16(ab + off, pa);
            CP_ASYNC16(bb + off, pb);
        }
    };

    float acc[4][4][4];
    #pragma unroll
    for (int mi = 0; mi < 4; mi++)
        #pragma unroll
        for (int ni = 0; ni < 4; ni++)
            #pragma unroll
            for (int j = 0; j < 4; j++) acc[mi][ni][j] = 0.f;

    // ldmatrix source addresses (constant per thread, plus stage/k offsets)
    const uint32_t a_lm = as_u32 + (uint32_t)(warp_m + (lane & 15)) * (SROW * 2) + ((lane >> 4) << 4);
    const int bq = lane >> 3;  // 0..3
    const uint32_t b_lm = bs_u32 + (uint32_t)(warp_n + ((bq >> 1) << 3) + (lane & 7)) * (SROW * 2)
                          + ((bq & 1) << 4);

    auto compute = [&](int bi) {
        uint32_t soff = (uint32_t)bi * STG_BYTES;
        #pragma unroll
        for (int ks = 0; ks < 2; ++ks) {        // two k16 steps (bytes: ks*32)
            uint32_t a[4][4], b[4][2];
            #pragma unroll
            for (int mi = 0; mi < 4; mi++)
                ldsm4(a[mi], a_lm + soff + (uint32_t)mi * 16 * (SROW * 2) + ks * 32);
            #pragma unroll
            for (int nb = 0; nb < 2; nb++) {
                uint32_t r[4];
                ldsm4(r, b_lm + soff + (uint32_t)nb * 16 * (SROW * 2) + ks * 32);
                b[nb * 2][0] = r[0]; b[nb * 2][1] = r[1];
                b[nb * 2 + 1][0] = r[2]; b[nb * 2 + 1][1] = r[3];
            }
            #pragma unroll
            for (int mi = 0; mi < 4; mi++)
                #pragma unroll
                for (int ni = 0; ni < 4; ni++)
                    mma16816(acc[mi][ni], a[mi], b[ni]);
        }
    };

    // prologue: 3 stages in flight
    gload_async(0); CP_COMMIT();
    gload_async(1); CP_COMMIT();
    gload_async(2); CP_COMMIT();

    for (int s = 0; s < 48; ++s) {
        CP_WAIT2();
        __syncthreads();
        if (s + 3 < 48) gload_async(s + 3);
        CP_COMMIT();
        compute(s & 3);
    }

    // epilogue: C fragment rows grp,+8; cols (lane&3)*2
    #pragma unroll
    for (int mi = 0; mi < 4; mi++) {
        int row0 = bm + warp_m + mi * 16 + (lane >> 2);
        #pragma unroll
        for (int ni = 0; ni < 4; ni++) {
            int col = bn + warp_n + ni * 8 + ((lane & 3) << 1);
            if (row0 < M)
                *(float2*)&C[(size_t)row0 * N + col] = make_float2(acc[mi][ni][0], acc[mi][ni][1]);
            if (row0 + 8 < M)
                *(float2*)&C[(size_t)(row0 + 8) * N + col] = make_float2(acc[mi][ni][2], acc[mi][ni][3]);
        }
    }
}

// ---------------- aggregation ----------------
// out[i] = bias + dis^2*Y[i] + sum val*Y[col]; optionally fused bf16 split into g_A2
template <int D, int RELU, int WB16, int WF32>
__global__ __launch_bounds__(256) void aggregate_kernel(
    const float* __restrict__ Y, float* __restrict__ out, const float* __restrict__ bias) {
    constexpr int TPN = D / 4;
    int gt = blockIdx.x * 256 + threadIdx.x;
    int node = gt / TPN;
    int lane = gt % TPN;
    if (node >= NN) return;
    int c = lane << 2;

    float dv = g_dis[node];
    float w = dv * dv;
    float4 acc = *(const float4*)(bias + c);
    float4 y = *(const float4*)(Y + (size_t)node * D + c);
    acc.x = fmaf(w, y.x, acc.x); acc.y = fmaf(w, y.y, acc.y);
    acc.z = fmaf(w, y.z, acc.z); acc.w = fmaf(w, y.w, acc.w);

    int e0 = g_rowptr[node], e1 = g_rowptr[node + 1];
    int p = e0;
    // unroll-by-4: batch the index loads and row gathers for MLP
    for (; p + 4 <= e1; p += 4) {
        int2 cv0 = __ldg(&g_colval[p + 0]);
        int2 cv1 = __ldg(&g_colval[p + 1]);
        int2 cv2 = __ldg(&g_colval[p + 2]);
        int2 cv3 = __ldg(&g_colval[p + 3]);
        float4 y0 = *(const float4*)(Y + (size_t)cv0.x * D + c);
        float4 y1 = *(const float4*)(Y + (size_t)cv1.x * D + c);
        float4 y2 = *(const float4*)(Y + (size_t)cv2.x * D + c);
        float4 y3 = *(const float4*)(Y + (size_t)cv3.x * D + c);
        float v0 = __int_as_float(cv0.y), v1 = __int_as_float(cv1.y);
        float v2 = __int_as_float(cv2.y), v3 = __int_as_float(cv3.y);
        acc.x = fmaf(v0, y0.x, acc.x); acc.y = fmaf(v0, y0.y, acc.y);
        acc.z = fmaf(v0, y0.z, acc.z); acc.w = fmaf(v0, y0.w, acc.w);
        acc.x = fmaf(v1, y1.x, acc.x); acc.y = fmaf(v1, y1.y, acc.y);
        acc.z = fmaf(v1, y1.z, acc.z); acc.w = fmaf(v1, y1.w, acc.w);
        acc.x = fmaf(v2, y2.x, acc.x); acc.y = fmaf(v2, y2.y, acc.y);
        acc.z = fmaf(v2, y2.z, acc.z); acc.w = fmaf(v2, y2.w, acc.w);
        acc.x = fmaf(v3, y3.x, acc.x); acc.y = fmaf(v3, y3.y, acc.y);
        acc.z = fmaf(v3, y3.z, acc.z); acc.w = fmaf(v3, y3.w, acc.w);
    }
    for (; p < e1; ++p) {
        int2 cv = __ldg(&g_colval[p]);
        float v = __int_as_float(cv.y);
        float4 yj = *(const float4*)(Y + (size_t)cv.x * D + c);
        acc.x = fmaf(v, yj.x, acc.x); acc.y = fmaf(v, yj.y, acc.y);
        acc.z = fmaf(v, yj.z, acc.z); acc.w = fmaf(v, yj.w, acc.w);
    }
    if (RELU) {
        acc.x = fmaxf(acc.x, 0.f); acc.y = fmaxf(acc.y, 0.f);
        acc.z = fmaxf(acc.z, 0.f); acc.w = fmaxf(acc.w, 0.f);
    }
    if (WF32) *(float4*)(out + (size_t)node * D + c) = acc;
    if (WB16) {
        uint2 hi, lo;
        split4(acc, hi, lo);
        *(uint2*)(g_A2 + (size_t)node * 1024 + c) = hi;
        *(uint2*)(g_A2 + (size_t)node * 1024 + 512 + c) = lo;
    }
}

// ---------------- SIMT GEMM for heads (f32x2) ----------------
__device__ __forceinline__ unsigned long long pack2f(float x) {
    unsigned long long r;
    asm("mov.b64 %0, {%1, %1};" : "=l"(r) : "f"(x));
    return r;
}
__device__ __forceinline__ void fma2(unsigned long long& acc, unsigned long long a, unsigned long long b) {
    asm("fma.rn.f32x2 %0, %1, %2, %0;" : "+l"(acc) : "l"(a), "l"(b));
}
__device__ __forceinline__ float2 unpack2(unsigned long long v) {
    float2 r;
    r.x = __uint_as_float((unsigned int)(v & 0xffffffffull));
    r.y = __uint_as_float((unsigned int)(v >> 32));
    return r;
}

__global__ __launch_bounds__(256) void gemm_kernel(
    const float* __restrict__ A, const float* __restrict__ B,
    float* __restrict__ C, const float* __restrict__ bias,
    int M, int N, int K) {
    __shared__ __align__(16) float As[2][16][132];
    __shared__ __align__(16) float Bs[2][16][128];

    const int tid = threadIdx.x;
    const int tx = tid & 15;
    const int ty = tid >> 4;
    const int bm = blockIdx.y * 128;
    const int bn = blockIdx.x * 128;

    const int arow = tid >> 2;
    const int ak = (tid & 3) << 2;
    const int brow = tid >> 5;
    const int bcol = (tid & 31) << 2;
    const bool fullN = (bn + 128 <= N);

    float4 a0, a1, b0, b1;
    auto gload = [&](int kt) {
        int r0 = bm + arow, r1 = r0 + 64;
        a0 = (r0 < M) ? *(const float4*)(A + (size_t)r0 * K + kt + ak) : make_float4(0.f, 0.f, 0.f, 0.f);
        a1 = (r1 < M) ? *(const float4*)(A + (size_t)r1 * K + kt + ak) : make_float4(0.f, 0.f, 0.f, 0.f);
        int c = bn + bcol;
        const float* Bp0 = B + (size_t)(kt + brow) * N;
        const float* Bp1 = B + (size_t)(kt + brow + 8) * N;
        if (fullN) { b0 = *(const float4*)(Bp0 + c); b1 = *(const float4*)(Bp1 + c); }
        else {
            b0.x = (c + 0 < N) ? Bp0[c + 0] : 0.f; b0.y = (c + 1 < N) ? Bp0[c + 1] : 0.f;
            b0.z = (c + 2 < N) ? Bp0[c + 2] : 0.f; b0.w = (c + 3 < N) ? Bp0[c + 3] : 0.f;
            b1.x = (c + 0 < N) ? Bp1[c + 0] : 0.f; b1.y = (c + 1 < N) ? Bp1[c + 1] : 0.f;
            b1.z = (c + 2 < N) ? Bp1[c + 2] : 0.f; b1.w = (c + 3 < N) ? Bp1[c + 3] : 0.f;
        }
    };
    auto sstore = [&](int bi) {
        As[bi][ak + 0][arow] = a0.x; As[bi][ak + 1][arow] = a0.y;
        As[bi][ak + 2][arow] = a0.z; As[bi][ak + 3][arow] = a0.w;
        As[bi][ak + 0][arow + 64] = a1.x; As[bi][ak + 1][arow + 64] = a1.y;
        As[bi][ak + 2][arow + 64] = a1.z; As[bi][ak + 3][arow + 64] = a1.w;
        *(float4*)&Bs[bi][brow][bcol] = b0;
        *(float4*)&Bs[bi][brow + 8][bcol] = b1;
    };

    unsigned long long acc[8][4];
    #pragma unroll
    for (int i = 0; i < 8; i++)
        #pragma unroll
        for (int j = 0; j < 4; j++) acc[i][j] = 0ull;

    auto compute = [&](int bi) {
        #pragma unroll
        for (int k = 0; k < 16; k++) {
            float4 av0 = *(const float4*)&As[bi][k][ty << 2];
            float4 av1 = *(const float4*)&As[bi][k][(ty << 2) + 64];
            ulonglong2 bv0 = *(const ulonglong2*)&Bs[bi][k][tx << 2];
            ulonglong2 bv1 = *(const ulonglong2*)&Bs[bi][k][(tx << 2) + 64];
            unsigned long long ap[8];
            ap[0] = pack2f(av0.x); ap[1] = pack2f(av0.y);
            ap[2] = pack2f(av0.z); ap[3] = pack2f(av0.w);
            ap[4] = pack2f(av1.x); ap[5] = pack2f(av1.y);
            ap[6] = pack2f(av1.z); ap[7] = pack2f(av1.w);
            #pragma unroll
            for (int m = 0; m < 8; m++) {
                fma2(acc[m][0], ap[m], bv0.x);
                fma2(acc[m][1], ap[m], bv0.y);
                fma2(acc[m][2], ap[m], bv1.x);
                fma2(acc[m][3], ap[m], bv1.y);
            }
        }
    };

    gload(0); sstore(0); __syncthreads();
    const int nT = K >> 4;
    int buf = 0;
    for (int t = 1; t < nT; ++t) {
        gload(t << 4);
        compute(buf);
        buf ^= 1;
        sstore(buf);
        __syncthreads();
    }
    compute(buf);

    #pragma unroll
    for (int mi = 0; mi < 8; mi++) {
        int r = bm + (ty << 2) + ((mi < 4) ? mi : (mi - 4 + 64));
        if (r >= M) continue;
        float* Crow = C + (size_t)r * N;
        #pragma unroll
        for (int p = 0; p < 4; p++) {
            int c = bn + (tx << 2) + ((p & 1) << 1) + ((p >> 1) << 6);
            float2 v = unpack2(acc[mi][p]);
            if (c < N) Crow[c] = v.x + (bias ? bias[c] : 0.f);
            if (c + 1 < N) Crow[c + 1] = v.y + (bias ? bias[c + 1] : 0.f);
        }
    }
}

// ---------------- head pack / split ----------------
__global__ void pack_heads_kernel(
    const float* __restrict__ We, const float* __restrict__ be,
    const float* __restrict__ Wh, const float* __restrict__ bh,
    const float* __restrict__ Wg, const float* __restrict__ bg) {
    int idx = blockIdx.x * blockDim.x + threadIdx.x;
    if (idx < 256 * 72) {
        int k = idx / 72, j = idx % 72;
        float v;
        if (j < 7) v = We[k * 7 + j];
        else if (j < 15) v = Wh[k * 8 + (j - 7)];
        else v = Wg[k * 57 + (j - 15)];
        g_Wall[idx] = v;
    }
    if (idx < 72) {
        float v;
        if (idx < 7) v = be[idx];
        else if (idx < 15) v = bh[idx - 7];
        else v = bg[idx - 15];
        g_ball[idx] = v;
    }
}

__global__ void split_heads_kernel(const float* __restrict__ T,
                                   float* __restrict__ outE,
                                   float* __restrict__ outH,
                                   float* __restrict__ outG) {
    int idx = blockIdx.x * blockDim.x + threadIdx.x;
    if (idx >= NN * 72) return;
    int i = idx / 72, j = idx % 72;
    float v = T[idx];
    if (j < 7) outE[i * 7 + j] = v;
    else if (j < 15) outH[i * 8 + (j - 7)] = v;
    else outG[i * 57 + (j - 15)] = v;
}

// ---------------- launch ----------------
extern "C" void kernel_launch(void* const* d_in, const int* in_sizes, int n_in,
                              void* d_out, int out_size) {
    const float* x  = (const float*)d_in[0];
    const int*   ei = (const int*)d_in[1];
    const float* W1 = (const float*)d_in[2];
    const float* b1 = (const float*)d_in[3];
    const float* W2 = (const float*)d_in[4];
    const float* b2 = (const float*)d_in[5];
    const float* W3 = (const float*)d_in[6];
    const float* b3 = (const float*)d_in[7];
    const float* We = (const float*)d_in[8];
    const float* be = (const float*)d_in[9];
    const float* Wh = (const float*)d_in[10];
    const float* bh = (const float*)d_in[11];
    const float* Wg = (const float*)d_in[12];
    const float* bg = (const float*)d_in[13];

    const int* srcArr = ei;
    const int* dstArr = ei + NE;

    float* out  = (float*)d_out;
    float* emb  = out;
    float* outE = out + (size_t)NN * 256;
    float* outH = outE + (size_t)NN * 7;
    float* outG = outH + (size_t)NN * 8;

    float *buf1, *buf2, *Wall, *ball;
    __nv_bfloat16 *A2, *Bt1, *Bt2, *Bt3;
    cudaGetSymbolAddress((void**)&buf1, g_buf1);
    cudaGetSymbolAddress((void**)&buf2, g_buf2);
    cudaGetSymbolAddress((void**)&Wall, g_Wall);
    cudaGetSymbolAddress((void**)&ball, g_ball);
    cudaGetSymbolAddress((void**)&A2,  g_A2);
    cudaGetSymbolAddress((void**)&Bt1, g_Bt1);
    cudaGetSymbolAddress((void**)&Bt2, g_Bt2);
    cudaGetSymbolAddress((void**)&Bt3, g_Bt3);

    const int GEMM_SMEM = 8 * STG_BYTES;  // 81920 B
    cudaFuncSetAttribute(gemm_mma_kernel, cudaFuncAttributeMaxDynamicSharedMemorySize, GEMM_SMEM);

    // weight conversions (independent of CSR)
    convert_B_kernel<<<(512 * 512 + 255) / 256, 256>>>(W1, Bt1, 512);
    convert_B_kernel<<<(512 * 512 + 255) / 256, 256>>>(W2, Bt2, 512);
    convert_B_kernel<<<(512 * 256 + 255) / 256, 256>>>(W3, Bt3, 256);

    // CSR build
    zero_indeg_kernel<<<(NN + 255) / 256, 256>>>();
    count_kernel<<<(NE + 255) / 256, 256>>>(dstArr);
    dis_kernel<<<(NN + 255) / 256, 256>>>();
    scan_part1<<<49, 1024>>>();
    scan_part2<<<1, 1>>>();
    scan_part3<<<49, 1024>>>();
    scatter_kernel<<<(NE + 255) / 256, 256>>>(srcArr, dstArr);

    const int gm = MPAD / 128;  // 391

    // layer 1
    convert_x_kernel<<<(MPAD * 128 + 255) / 256, 256>>>(x);
    gemm_mma_kernel<<<dim3(4, gm), 256, GEMM_SMEM>>>(A2, Bt1, buf1, NN, 512);
    aggregate_kernel<512, 1, 1, 0><<<NN / 2, 256>>>(buf1, nullptr, b1);  // -> g_A2 (bf16 split)
    // layer 2
    gemm_mma_kernel<<<dim3(4, gm), 256, GEMM_SMEM>>>(A2, Bt2, buf1, NN, 512);
    aggregate_kernel<512, 1, 1, 0><<<NN / 2, 256>>>(buf1, nullptr, b2);  // -> g_A2 (bf16 split)
    // layer 3 (emb f32, no relu)
    gemm_mma_kernel<<<dim3(2, gm), 256, GEMM_SMEM>>>(A2, Bt3, buf1, NN, 256);
    aggregate_kernel<256, 0, 0, 1><<<NN / 4, 256>>>(buf1, emb, b3);
    // heads
    pack_heads_kernel<<<(256 * 72 + 255) / 256, 256>>>(We, be, Wh, bh, Wg, bg);
    gemm_kernel<<<dim3(1, (NN + 127) / 128), 256>>>(emb, Wall, buf2, ball, NN, 72, 256);
    split_heads_kernel<<<(NN * 72 + 255) / 256, 256>>>(buf2, outE, outH, outG);
}

// round 9
// speedup vs baseline: 1.1963x; 1.1963x over previous
#include <cuda_runtime.h>
#include <cuda_bf16.h>
#include <cuda_fp16.h>
#include <math.h>
#include <stdint.h>

#define NN 50000
#define NE 800000
#define MPAD 50048   // 391 * 128

// ---------------- device scratch (allocation-free) ----------------
__device__ float g_buf1[NN * 512];          // GEMM output (f32 / half alias)
__device__ float g_buf2[NN * 512];          // heads bf16-split A source (alias)
__device__ __nv_bfloat16 g_A2[(size_t)MPAD * 1024];   // [Ah | Al] bf16, K-contig rows
__device__ __nv_bfloat16 g_Bt1[512 * 1024];           // [Bh | Bl], N-major rows, K-contig
__device__ __nv_bfloat16 g_Bt2[512 * 1024];
__device__ __nv_bfloat16 g_Bt3[256 * 1024];
__device__ __nv_bfloat16 g_Whd[128 * 512];            // heads B: [hi 256 | lo 256], rows>=72 zero
__device__ float g_dis[NN];
__device__ int   g_indeg[NN];
__device__ int   g_rowptr[NN + 1];
__device__ int   g_cursor[NN];
__device__ int2  g_colval[NE];              // (col, val bits)
__device__ float g_ball[72];
__device__ int   g_blocksum[64];

// ---------------- helpers ----------------
__device__ __forceinline__ uint32_t smem_u32(const void* p) {
    uint32_t a;
    asm("{ .reg .u64 t; cvta.to.shared.u64 t, %1; cvt.u32.u64 %0, t; }" : "=r"(a) : "l"(p));
    return a;
}
__device__ __forceinline__ void ldsm4(uint32_t* r, uint32_t addr) {
    asm volatile("ldmatrix.sync.aligned.m8n8.x4.shared.b16 {%0,%1,%2,%3}, [%4];"
                 : "=r"(r[0]), "=r"(r[1]), "=r"(r[2]), "=r"(r[3]) : "r"(addr));
}
__device__ __forceinline__ void mma16816(float* c, const uint32_t* a, const uint32_t* b) {
    asm volatile("mma.sync.aligned.m16n8k16.row.col.f32.bf16.bf16.f32 "
                 "{%0,%1,%2,%3}, {%4,%5,%6,%7}, {%8,%9}, {%0,%1,%2,%3};"
                 : "+f"(c[0]), "+f"(c[1]), "+f"(c[2]), "+f"(c[3])
                 : "r"(a[0]), "r"(a[1]), "r"(a[2]), "r"(a[3]), "r"(b[0]), "r"(b[1]));
}
#define CP_ASYNC16(dst, src) \
    asm volatile("cp.async.cg.shared.global [%0], [%1], 16;" :: "r"(dst), "l"(src))
#define CP_COMMIT() asm volatile("cp.async.commit_group;" ::: "memory")
#define CP_WAIT2()  asm volatile("cp.async.wait_group 2;" ::: "memory")

// ---------------- CSR build ----------------
__global__ void zero_indeg_kernel() {
    int i = blockIdx.x * blockDim.x + threadIdx.x;
    if (i < NN) g_indeg[i] = 0;
}
__global__ void count_kernel(const int* __restrict__ dst) {
    int e = blockIdx.x * blockDim.x + threadIdx.x;
    if (e < NE) atomicAdd(&g_indeg[dst[e]], 1);
}
__global__ void dis_kernel() {
    int i = blockIdx.x * blockDim.x + threadIdx.x;
    if (i < NN) g_dis[i] = rsqrtf((float)(g_indeg[i] + 1));
}
__global__ void scan_part1() {
    __shared__ int ws[32];
    int i = blockIdx.x * 1024 + threadIdx.x;
    int v = (i < NN) ? g_indeg[i] : 0;
    #pragma unroll
    for (int o = 16; o > 0; o >>= 1) v += __shfl_down_sync(0xffffffffu, v, o);
    if ((threadIdx.x & 31) == 0) ws[threadIdx.x >> 5] = v;
    __syncthreads();
    if (threadIdx.x < 32) {
        int s = ws[threadIdx.x];
        #pragma unroll
        for (int o = 16; o > 0; o >>= 1) s += __shfl_down_sync(0xffffffffu, s, o);
        if (threadIdx.x == 0) g_blocksum[blockIdx.x] = s;
    }
}
__global__ void scan_part2() {
    int acc = 0;
    for (int b = 0; b < 49; ++b) { int t = g_blocksum[b]; g_blocksum[b] = acc; acc += t; }
    g_rowptr[NN] = acc;
}
__global__ void scan_part3() {
    __shared__ int ws[32];
    int tid = threadIdx.x;
    int i = blockIdx.x * 1024 + tid;
    int v = (i < NN) ? g_indeg[i] : 0;
    int x = v;
    #pragma unroll
    for (int o = 1; o < 32; o <<= 1) {
        int t = __shfl_up_sync(0xffffffffu, x, o);
        if ((tid & 31) >= o) x += t;
    }
    if ((tid & 31) == 31) ws[tid >> 5] = x;
    __syncthreads();
    if (tid < 32) {
        int s = ws[tid];
        #pragma unroll
        for (int o = 1; o < 32; o <<= 1) {
            int t = __shfl_up_sync(0xffffffffu, s, o);
            if (tid >= o) s += t;
        }
        ws[tid] = s;
    }
    __syncthreads();
    int wofs = (tid >= 32) ? ws[(tid >> 5) - 1] : 0;
    int excl = x + wofs - v + g_blocksum[blockIdx.x];
    if (i < NN) { g_rowptr[i] = excl; g_cursor[i] = excl; }
}
__global__ void scatter_kernel(const int* __restrict__ src, const int* __restrict__ dst) {
    int e = blockIdx.x * blockDim.x + threadIdx.x;
    if (e < NE) {
        int s = src[e], d = dst[e];
        int p = atomicAdd(&g_cursor[d], 1);
        g_colval[p] = make_int2(s, __float_as_int(g_dis[s] * g_dis[d]));
    }
}

// ---------------- bf16 split conversions ----------------
__device__ __forceinline__ uint32_t pack_bf2(float a, float b) {
    __nv_bfloat162 h = __floats2bfloat162_rn(a, b);
    return *(uint32_t*)&h;
}
__device__ __forceinline__ void split4(const float4& v, uint2& hi, uint2& lo) {
    __nv_bfloat16 hx = __float2bfloat16_rn(v.x), hy = __float2bfloat16_rn(v.y);
    __nv_bfloat16 hz = __float2bfloat16_rn(v.z), hw = __float2bfloat16_rn(v.w);
    float lx = v.x - __bfloat162float(hx), ly = v.y - __bfloat162float(hy);
    float lz = v.z - __bfloat162float(hz), lw = v.w - __bfloat162float(hw);
    __nv_bfloat162 h01 = __floats2bfloat162_rn(__bfloat162float(hx), __bfloat162float(hy));
    __nv_bfloat162 h23 = __floats2bfloat162_rn(__bfloat162float(hz), __bfloat162float(hw));
    hi.x = *(uint32_t*)&h01; hi.y = *(uint32_t*)&h23;
    lo.x = pack_bf2(lx, ly); lo.y = pack_bf2(lz, lw);
}

__global__ void convert_x_kernel(const float* __restrict__ X) {
    int idx = blockIdx.x * 256 + threadIdx.x;
    if (idx >= MPAD * 128) return;
    int row = idx >> 7, col = (idx & 127) << 2;
    uint2 hi = make_uint2(0, 0), lo = make_uint2(0, 0);
    if (row < NN) {
        float4 v = *(const float4*)(X + (size_t)row * 512 + col);
        split4(v, hi, lo);
    }
    *(uint2*)(g_A2 + (size_t)row * 1024 + col) = hi;
    *(uint2*)(g_A2 + (size_t)row * 1024 + 512 + col) = lo;
}

// W [K=512][N] f32 -> Bt [N][1024] bf16 ([Bh|Bl]), N-major rows
__global__ void convert_B_kernel(const float* __restrict__ W, __nv_bfloat16* __restrict__ Bt, int N) {
    int idx = blockIdx.x * 256 + threadIdx.x;
    if (idx >= 512 * N) return;
    int k = idx / N, n = idx % N;
    float v = W[idx];
    __nv_bfloat16 hi = __float2bfloat16_rn(v);
    float l = v - __bfloat162float(hi);
    Bt[(size_t)n * 1024 + k] = hi;
    Bt[(size_t)n * 1024 + 512 + k] = __float2bfloat16_rn(l);
}

// heads weights -> g_Whd [128 rows][512] bf16 split ([hi 256|lo 256]); rows >= 72 zero. + g_ball
__global__ void pack_heads_kernel(
    const float* __restrict__ We, const float* __restrict__ be,
    const float* __restrict__ Wh, const float* __restrict__ bh,
    const float* __restrict__ Wg, const float* __restrict__ bg) {
    int idx = blockIdx.x * blockDim.x + threadIdx.x;
    if (idx < 128 * 256) {
        int n = idx >> 8, k = idx & 255;
        float v = 0.f;
        if (n < 7) v = We[k * 7 + n];
        else if (n < 15) v = Wh[k * 8 + (n - 7)];
        else if (n < 72) v = Wg[k * 57 + (n - 15)];
        __nv_bfloat16 hi = __float2bfloat16_rn(v);
        float l = v - __bfloat162float(hi);
        g_Whd[n * 512 + k] = hi;
        g_Whd[n * 512 + 256 + k] = __float2bfloat16_rn(l);
    }
    if (idx < 72) {
        float v;
        if (idx < 7) v = be[idx];
        else if (idx < 15) v = bh[idx - 7];
        else v = bg[idx - 15];
        g_ball[idx] = v;
    }
}

// ---------------- mma.sync GEMM: C[M,N] = A2 @ Bt^T (3-term bf16 split, fp32 accum) ----
// A2: [M, 2*TERMK] bf16. Bt: [N, 2*TERMK] bf16. 3*TERMK/32 K-stages of 32.
// CTA 128x128, 8 warps of 64x32. 4-stage cp.async pipeline. OutT = float or __half.
#define SROW 40
#define STG_BYTES (128 * SROW * 2)   // 10240 B per tile per stage
template <int TERMK, typename OutT>
__global__ __launch_bounds__(256) void gemm_mma_kernel(
    const __nv_bfloat16* __restrict__ A2, const __nv_bfloat16* __restrict__ Bt,
    OutT* __restrict__ C, int M, int N)
{
    extern __shared__ __align__(16) __nv_bfloat16 dsmem[];
    const uint32_t as_u32 = smem_u32(dsmem);
    const uint32_t bs_u32 = as_u32 + 4 * STG_BYTES;

    constexpr int NSTG = 3 * TERMK / 32;
    constexpr int TPS = TERMK / 32;   // stages per term
    constexpr int RS = 2 * TERMK;     // row stride (elems)

    const int tid = threadIdx.x;
    const int wid = tid >> 5, lane = tid & 31;
    const int bm = blockIdx.y * 128;
    const int bn = blockIdx.x * 128;
    const int warp_m = (wid >> 2) * 64;
    const int warp_n = (wid & 3) * 32;

    const int lrow = tid >> 2;
    const int lseg = (tid & 3) << 3;

    auto gload_async = [&](int s) {
        int term = s / TPS, kk = (s % TPS) << 5;
        int ac = ((term == 1) ? TERMK : 0) + kk;   // A terms: Ah, Al, Ah
        int bc = ((term == 2) ? TERMK : 0) + kk;   // B terms: Bh, Bh, Bl
        uint32_t ab = as_u32 + (uint32_t)(s & 3) * STG_BYTES;
        uint32_t bb = bs_u32 + (uint32_t)(s & 3) * STG_BYTES;
        #pragma unroll
        for (int i = 0; i < 2; ++i) {
            int row = lrow + i * 64;
            const __nv_bfloat16* pa = A2 + (size_t)(bm + row) * RS + ac + lseg;
            const __nv_bfloat16* pb = Bt + (size_t)(bn + row) * RS + bc + lseg;
            uint32_t off = (uint32_t)(row * SROW + lseg) * 2;
            CP_ASYNC16(ab + off, pa);
            CP_ASYNC16(bb + off, pb);
        }
    };

    float acc[4][4][4];
    #pragma unroll
    for (int mi = 0; mi < 4; mi++)
        #pragma unroll
        for (int ni = 0; ni < 4; ni++)
            #pragma unroll
            for (int j = 0; j < 4; j++) acc[mi][ni][j] = 0.f;

    const uint32_t a_lm = as_u32 + (uint32_t)(warp_m + (lane & 15)) * (SROW * 2) + ((lane >> 4) << 4);
    const int bq = lane >> 3;
    const uint32_t b_lm = bs_u32 + (uint32_t)(warp_n + ((bq >> 1) << 3) + (lane & 7)) * (SROW * 2)
                          + ((bq & 1) << 4);

    auto compute = [&](int bi) {
        uint32_t soff = (uint32_t)bi * STG_BYTES;
        #pragma unroll
        for (int ks = 0; ks < 2; ++ks) {
            uint32_t a[4][4], b[4][2];
            #pragma unroll
            for (int mi = 0; mi < 4; mi++)
                ldsm4(a[mi], a_lm + soff + (uint32_t)mi * 16 * (SROW * 2) + ks * 32);
            #pragma unroll
            for (int nb = 0; nb < 2; nb++) {
                uint32_t r[4];
                ldsm4(r, b_lm + soff + (uint32_t)nb * 16 * (SROW * 2) + ks * 32);
                b[nb * 2][0] = r[0]; b[nb * 2][1] = r[1];
                b[nb * 2 + 1][0] = r[2]; b[nb * 2 + 1][1] = r[3];
            }
            #pragma unroll
            for (int mi = 0; mi < 4; mi++)
                #pragma unroll
                for (int ni = 0; ni < 4; ni++)
                    mma16816(acc[mi][ni], a[mi], b[ni]);
        }
    };

    gload_async(0); CP_COMMIT();
    gload_async(1); CP_COMMIT();
    gload_async(2); CP_COMMIT();

    for (int s = 0; s < NSTG; ++s) {
        CP_WAIT2();
        __syncthreads();
        if (s + 3 < NSTG) gload_async(s + 3);
        CP_COMMIT();
        compute(s & 3);
    }

    #pragma unroll
    for (int mi = 0; mi < 4; mi++) {
        int row0 = bm + warp_m + mi * 16 + (lane >> 2);
        #pragma unroll
        for (int ni = 0; ni < 4; ni++) {
            int col = bn + warp_n + ni * 8 + ((lane & 3) << 1);
            if (row0 < M) {
                if (sizeof(OutT) == 4)
                    *(float2*)&(((float*)C)[(size_t)row0 * N + col]) =
                        make_float2(acc[mi][ni][0], acc[mi][ni][1]);
                else {
                    __half2 h = __floats2half2_rn(acc[mi][ni][0], acc[mi][ni][1]);
                    *(__half2*)&(((__half*)C)[(size_t)row0 * N + col]) = h;
                }
            }
            if (row0 + 8 < M) {
                if (sizeof(OutT) == 4)
                    *(float2*)&(((float*)C)[(size_t)(row0 + 8) * N + col]) =
                        make_float2(acc[mi][ni][2], acc[mi][ni][3]);
                else {
                    __half2 h = __floats2half2_rn(acc[mi][ni][2], acc[mi][ni][3]);
                    *(__half2*)&(((__half*)C)[(size_t)(row0 + 8) * N + col]) = h;
                }
            }
        }
    }
}

// ---------------- aggregation (hidden layers, fp16 gather, D=512) ----------------
// h = relu(bias + dis^2*Y[i] + sum val*Y[col]); writes bf16 split into g_A2.
__global__ __launch_bounds__(256) void aggregate_h_kernel(
    const __half* __restrict__ Y, const float* __restrict__ bias) {
    int gt = blockIdx.x * 256 + threadIdx.x;
    int node = gt >> 6;          // 64 threads/node
    int lane = gt & 63;
    if (node >= NN) return;
    int c = lane << 3;           // 8 elems/thread

    float acc[8];
    float dv = g_dis[node];
    float w = dv * dv;
    {
        float4 b0 = *(const float4*)(bias + c);
        float4 b1 = *(const float4*)(bias + c + 4);
        uint4 raw = *(const uint4*)(Y + (size_t)node * 512 + c);
        const __half2* h = (const __half2*)&raw;
        float2 f0 = __half22float2(h[0]), f1 = __half22float2(h[1]);
        float2 f2 = __half22float2(h[2]), f3 = __half22float2(h[3]);
        acc[0] = fmaf(w, f0.x, b0.x); acc[1] = fmaf(w, f0.y, b0.y);
        acc[2] = fmaf(w, f1.x, b0.z); acc[3] = fmaf(w, f1.y, b0.w);
        acc[4] = fmaf(w, f2.x, b1.x); acc[5] = fmaf(w, f2.y, b1.y);
        acc[6] = fmaf(w, f3.x, b1.z); acc[7] = fmaf(w, f3.y, b1.w);
    }

    int e0 = g_rowptr[node], e1 = g_rowptr[node + 1];
    int p = e0;
    for (; p + 2 <= e1; p += 2) {
        int2 cv0 = __ldg(&g_colval[p + 0]);
        int2 cv1 = __ldg(&g_colval[p + 1]);
        uint4 r0 = *(const uint4*)(Y + (size_t)cv0.x * 512 + c);
        uint4 r1 = *(const uint4*)(Y + (size_t)cv1.x * 512 + c);
        float v0 = __int_as_float(cv0.y), v1 = __int_as_float(cv1.y);
        const __half2* h0 = (const __half2*)&r0;
        const __half2* h1 = (const __half2*)&r1;
        #pragma unroll
        for (int q = 0; q < 4; ++q) {
            float2 f0 = __half22float2(h0[q]);
            float2 f1 = __half22float2(h1[q]);
            acc[q * 2 + 0] = fmaf(v0, f0.x, acc[q * 2 + 0]);
            acc[q * 2 + 1] = fmaf(v0, f0.y, acc[q * 2 + 1]);
            acc[q * 2 + 0] = fmaf(v1, f1.x, acc[q * 2 + 0]);
            acc[q * 2 + 1] = fmaf(v1, f1.y, acc[q * 2 + 1]);
        }
    }
    for (; p < e1; ++p) {
        int2 cv = __ldg(&g_colval[p]);
        float v = __int_as_float(cv.y);
        uint4 r = *(const uint4*)(Y + (size_t)cv.x * 512 + c);
        const __half2* h = (const __half2*)&r;
        #pragma unroll
        for (int q = 0; q < 4; ++q) {
            float2 f = __half22float2(h[q]);
            acc[q * 2 + 0] = fmaf(v, f.x, acc[q * 2 + 0]);
            acc[q * 2 + 1] = fmaf(v, f.y, acc[q * 2 + 1]);
        }
    }
    #pragma unroll
    for (int q = 0; q < 8; ++q) acc[q] = fmaxf(acc[q], 0.f);

    // bf16 split -> g_A2
    uint4 hi, lo;
    {
        uint2 h0, l0, h1, l1;
        split4(make_float4(acc[0], acc[1], acc[2], acc[3]), h0, l0);
        split4(make_float4(acc[4], acc[5], acc[6], acc[7]), h1, l1);
        hi.x = h0.x; hi.y = h0.y; hi.z = h1.x; hi.w = h1.y;
        lo.x = l0.x; lo.y = l0.y; lo.z = l1.x; lo.w = l1.y;
    }
    *(uint4*)(g_A2 + (size_t)node * 1024 + c) = hi;
    *(uint4*)(g_A2 + (size_t)node * 1024 + 512 + c) = lo;
}

// ---------------- layer-3 aggregation (f32, D=256) -> emb + heads bf16 split ----------------
__global__ __launch_bounds__(256) void aggregate3_kernel(
    const float* __restrict__ Y, float* __restrict__ emb, const float* __restrict__ bias,
    __nv_bfloat16* __restrict__ Ahd) {
    int gt = blockIdx.x * 256 + threadIdx.x;
    int node = gt >> 6;          // 64 threads/node
    int lane = gt & 63;
    if (node >= NN) return;
    int c = lane << 2;

    float dv = g_dis[node];
    float w = dv * dv;
    float4 acc = *(const float4*)(bias + c);
    float4 y = *(const float4*)(Y + (size_t)node * 256 + c);
    acc.x = fmaf(w, y.x, acc.x); acc.y = fmaf(w, y.y, acc.y);
    acc.z = fmaf(w, y.z, acc.z); acc.w = fmaf(w, y.w, acc.w);

    int e0 = g_rowptr[node], e1 = g_rowptr[node + 1];
    int p = e0;
    for (; p + 2 <= e1; p += 2) {
        int2 cv0 = __ldg(&g_colval[p + 0]);
        int2 cv1 = __ldg(&g_colval[p + 1]);
        float4 y0 = *(const float4*)(Y + (size_t)cv0.x * 256 + c);
        float4 y1 = *(const float4*)(Y + (size_t)cv1.x * 256 + c);
        float v0 = __int_as_float(cv0.y), v1 = __int_as_float(cv1.y);
        acc.x = fmaf(v0, y0.x, acc.x); acc.y = fmaf(v0, y0.y, acc.y);
        acc.z = fmaf(v0, y0.z, acc.z); acc.w = fmaf(v0, y0.w, acc.w);
        acc.x = fmaf(v1, y1.x, acc.x); acc.y = fmaf(v1, y1.y, acc.y);
        acc.z = fmaf(v1, y1.z, acc.z); acc.w = fmaf(v1, y1.w, acc.w);
    }
    for (; p < e1; ++p) {
        int2 cv = __ldg(&g_colval[p]);
        float v = __int_as_float(cv.y);
        float4 yj = *(const float4*)(Y + (size_t)cv.x * 256 + c);
        acc.x = fmaf(v, yj.x, acc.x); acc.y = fmaf(v, yj.y, acc.y);
        acc.z = fmaf(v, yj.z, acc.z); acc.w = fmaf(v, yj.w, acc.w);
    }
    *(float4*)(emb + (size_t)node * 256 + c) = acc;
    uint2 hi, lo;
    split4(acc, hi, lo);
    *(uint2*)(Ahd + (size_t)node * 512 + c) = hi;
    *(uint2*)(Ahd + (size_t)node * 512 + 256 + c) = lo;
}

// ---------------- head output split (adds bias) ----------------
__global__ void split_heads_kernel(const float* __restrict__ T,
                                   float* __restrict__ outE,
                                   float* __restrict__ outH,
                                   float* __restrict__ outG) {
    int idx = blockIdx.x * blockDim.x + threadIdx.x;
    if (idx >= NN * 72) return;
    int i = idx / 72, j = idx % 72;
    float v = T[(size_t)i * 128 + j] + g_ball[j];
    if (j < 7) outE[i * 7 + j] = v;
    else if (j < 15) outH[i * 8 + (j - 7)] = v;
    else outG[i * 57 + (j - 15)] = v;
}

// ---------------- launch ----------------
extern "C" void kernel_launch(void* const* d_in, const int* in_sizes, int n_in,
                              void* d_out, int out_size) {
    const float* x  = (const float*)d_in[0];
    const int*   ei = (const int*)d_in[1];
    const float* W1 = (const float*)d_in[2];
    const float* b1 = (const float*)d_in[3];
    const float* W2 = (const float*)d_in[4];
    const float* b2 = (const float*)d_in[5];
    const float* W3 = (const float*)d_in[6];
    const float* b3 = (const float*)d_in[7];
    const float* We = (const float*)d_in[8];
    const float* be = (const float*)d_in[9];
    const float* Wh = (const float*)d_in[10];
    const float* bh = (const float*)d_in[11];
    const float* Wg = (const float*)d_in[12];
    const float* bg = (const float*)d_in[13];

    const int* srcArr = ei;
    const int* dstArr = ei + NE;

    float* out  = (float*)d_out;
    float* emb  = out;
    float* outE = out + (size_t)NN * 256;
    float* outH = outE + (size_t)NN * 7;
    float* outG = outH + (size_t)NN * 8;

    float *buf1, *buf2;
    __nv_bfloat16 *A2, *Bt1, *Bt2, *Bt3, *Whd;
    cudaGetSymbolAddress((void**)&buf1, g_buf1);
    cudaGetSymbolAddress((void**)&buf2, g_buf2);
    cudaGetSymbolAddress((void**)&A2,  g_A2);
    cudaGetSymbolAddress((void**)&Bt1, g_Bt1);
    cudaGetSymbolAddress((void**)&Bt2, g_Bt2);
    cudaGetSymbolAddress((void**)&Bt3, g_Bt3);
    cudaGetSymbolAddress((void**)&Whd, g_Whd);

    const int GEMM_SMEM = 8 * STG_BYTES;  // 81920 B
    cudaFuncSetAttribute(gemm_mma_kernel<512, __half>, cudaFuncAttributeMaxDynamicSharedMemorySize, GEMM_SMEM);
    cudaFuncSetAttribute(gemm_mma_kernel<512, float>,  cudaFuncAttributeMaxDynamicSharedMemorySize, GEMM_SMEM);
    cudaFuncSetAttribute(gemm_mma_kernel<256, float>,  cudaFuncAttributeMaxDynamicSharedMemorySize, GEMM_SMEM);

    // weight conversions (independent of CSR)
    convert_B_kernel<<<(512 * 512 + 255) / 256, 256>>>(W1, Bt1, 512);
    convert_B_kernel<<<(512 * 512 + 255) / 256, 256>>>(W2, Bt2, 512);
    convert_B_kernel<<<(512 * 256 + 255) / 256, 256>>>(W3, Bt3, 256);
    pack_heads_kernel<<<(128 * 256 + 255) / 256, 256>>>(We, be, Wh, bh, Wg, bg);

    // CSR build
    zero_indeg_kernel<<<(NN + 255) / 256, 256>>>();
    count_kernel<<<(NE + 255) / 256, 256>>>(dstArr);
    dis_kernel<<<(NN + 255) / 256, 256>>>();
    scan_part1<<<49, 1024>>>();
    scan_part2<<<1, 1>>>();
    scan_part3<<<49, 1024>>>();
    scatter_kernel<<<(NE + 255) / 256, 256>>>(srcArr, dstArr);

    const int gm = MPAD / 128;  // 391
    __half* bufh = (__half*)buf1;
    __nv_bfloat16* Ahd = (__nv_bfloat16*)buf2;

    // layer 1 (fp16 Y)
    convert_x_kernel<<<(MPAD * 128 + 255) / 256, 256>>>(x);
    gemm_mma_kernel<512, __half><<<dim3(4, gm), 256, GEMM_SMEM>>>(A2, Bt1, bufh, NN, 512);
    aggregate_h_kernel<<<NN / 4, 256>>>(bufh, b1);   // -> g_A2 (bf16 split)
    // layer 2 (fp16 Y)
    gemm_mma_kernel<512, __half><<<dim3(4, gm), 256, GEMM_SMEM>>>(A2, Bt2, bufh, NN, 512);
    aggregate_h_kernel<<<NN / 4, 256>>>(bufh, b2);   // -> g_A2 (bf16 split)
    // layer 3 (f32 Y, emb output)
    gemm_mma_kernel<512, float><<<dim3(2, gm), 256, GEMM_SMEM>>>(A2, Bt3, buf1, NN, 256);
    aggregate3_kernel<<<NN / 4, 256>>>(buf1, emb, b3, Ahd);
    // heads: mma GEMM [NN,512split] @ Whd[128,512split] -> buf1 [NN,128]
    gemm_mma_kernel<256, float><<<dim3(1, gm), 256, GEMM_SMEM>>>(Ahd, Whd, buf1, NN, 128);
    split_heads_kernel<<<(NN * 72 + 255) / 256, 256>>>(buf1, outE, outH, outG);
}

// round 10
// speedup vs baseline: 1.5876x; 1.3271x over previous
#include <cuda_runtime.h>
#include <cuda_bf16.h>
#include <cuda_fp16.h>
#include <math.h>
#include <stdint.h>

#define NN 50000
#define NE 800000
#define MPAD 50048   // 391 * 128

// ---------------- device scratch (allocation-free) ----------------
__device__ float g_buf1[NN * 512];          // GEMM output buffer (f32 / fp16 alias)
__device__ float g_buf2[NN * 512];          // heads A (fp16 alias) / spare
__device__ __half g_Ah[(size_t)MPAD * 512]; // fp16 activations (GEMM A operand)
__device__ __half g_Bt1[512 * 1024];        // [Bh | Bl] fp16, N-major rows, K-contig
__device__ __half g_Bt2[512 * 1024];
__device__ __half g_Bt3[256 * 1024];
__device__ __half g_Whd[128 * 512];         // heads B: [hi 256 | lo 256], rows>=72 zero
__device__ float g_dis[NN];
__device__ int   g_indeg[NN];
__device__ int   g_rowptr[NN + 1];
__device__ int   g_cursor[NN];
__device__ int2  g_colval[NE];              // (col, val bits)
__device__ float g_ball[72];
__device__ int   g_blocksum[64];

// ---------------- helpers ----------------
__device__ __forceinline__ uint32_t smem_u32(const void* p) {
    uint32_t a;
    asm("{ .reg .u64 t; cvta.to.shared.u64 t, %1; cvt.u32.u64 %0, t; }" : "=r"(a) : "l"(p));
    return a;
}
__device__ __forceinline__ void ldsm4(uint32_t* r, uint32_t addr) {
    asm volatile("ldmatrix.sync.aligned.m8n8.x4.shared.b16 {%0,%1,%2,%3}, [%4];"
                 : "=r"(r[0]), "=r"(r[1]), "=r"(r[2]), "=r"(r[3]) : "r"(addr));
}
__device__ __forceinline__ void mma16816(float* c, const uint32_t* a, const uint32_t* b) {
    asm volatile("mma.sync.aligned.m16n8k16.row.col.f32.f16.f16.f32 "
                 "{%0,%1,%2,%3}, {%4,%5,%6,%7}, {%8,%9}, {%0,%1,%2,%3};"
                 : "+f"(c[0]), "+f"(c[1]), "+f"(c[2]), "+f"(c[3])
                 : "r"(a[0]), "r"(a[1]), "r"(a[2]), "r"(a[3]), "r"(b[0]), "r"(b[1]));
}
#define CP_ASYNC16(dst, src) \
    asm volatile("cp.async.cg.shared.global [%0], [%1], 16;" :: "r"(dst), "l"(src))
#define CP_COMMIT() asm volatile("cp.async.commit_group;" ::: "memory")
#define CP_WAIT2()  asm volatile("cp.async.wait_group 2;" ::: "memory")

// ---------------- CSR build ----------------
__global__ void zero_indeg_kernel() {
    int i = blockIdx.x * blockDim.x + threadIdx.x;
    if (i < NN) g_indeg[i] = 0;
}
__global__ void count_kernel(const int* __restrict__ dst) {
    int e = blockIdx.x * blockDim.x + threadIdx.x;
    if (e < NE) atomicAdd(&g_indeg[dst[e]], 1);
}
__global__ void dis_kernel() {
    int i = blockIdx.x * blockDim.x + threadIdx.x;
    if (i < NN) g_dis[i] = rsqrtf((float)(g_indeg[i] + 1));
}
__global__ void scan_part1() {
    __shared__ int ws[32];
    int i = blockIdx.x * 1024 + threadIdx.x;
    int v = (i < NN) ? g_indeg[i] : 0;
    #pragma unroll
    for (int o = 16; o > 0; o >>= 1) v += __shfl_down_sync(0xffffffffu, v, o);
    if ((threadIdx.x & 31) == 0) ws[threadIdx.x >> 5] = v;
    __syncthreads();
    if (threadIdx.x < 32) {
        int s = ws[threadIdx.x];
        #pragma unroll
        for (int o = 16; o > 0; o >>= 1) s += __shfl_down_sync(0xffffffffu, s, o);
        if (threadIdx.x == 0) g_blocksum[blockIdx.x] = s;
    }
}
__global__ void scan_part2() {
    int acc = 0;
    for (int b = 0; b < 49; ++b) { int t = g_blocksum[b]; g_blocksum[b] = acc; acc += t; }
    g_rowptr[NN] = acc;
}
__global__ void scan_part3() {
    __shared__ int ws[32];
    int tid = threadIdx.x;
    int i = blockIdx.x * 1024 + tid;
    int v = (i < NN) ? g_indeg[i] : 0;
    int x = v;
    #pragma unroll
    for (int o = 1; o < 32; o <<= 1) {
        int t = __shfl_up_sync(0xffffffffu, x, o);
        if ((tid & 31) >= o) x += t;
    }
    if ((tid & 31) == 31) ws[tid >> 5] = x;
    __syncthreads();
    if (tid < 32) {
        int s = ws[tid];
        #pragma unroll
        for (int o = 1; o < 32; o <<= 1) {
            int t = __shfl_up_sync(0xffffffffu, s, o);
            if (tid >= o) s += t;
        }
        ws[tid] = s;
    }
    __syncthreads();
    int wofs = (tid >= 32) ? ws[(tid >> 5) - 1] : 0;
    int excl = x + wofs - v + g_blocksum[blockIdx.x];
    if (i < NN) { g_rowptr[i] = excl; g_cursor[i] = excl; }
}
__global__ void scatter_kernel(const int* __restrict__ src, const int* __restrict__ dst) {
    int e = blockIdx.x * blockDim.x + threadIdx.x;
    if (e < NE) {
        int s = src[e], d = dst[e];
        int p = atomicAdd(&g_cursor[d], 1);
        g_colval[p] = make_int2(s, __float_as_int(g_dis[s] * g_dis[d]));
    }
}

// ---------------- conversions ----------------
// x f32 [NN,512] -> fp16 [MPAD,512], pad rows zero
__global__ void convert_x_kernel(const float* __restrict__ X) {
    int idx = blockIdx.x * 256 + threadIdx.x;
    if (idx >= MPAD * 128) return;
    int row = idx >> 7, col = (idx & 127) << 2;
    uint2 o = make_uint2(0, 0);
    if (row < NN) {
        float4 v = *(const float4*)(X + (size_t)row * 512 + col);
        __half2 h0 = __floats2half2_rn(v.x, v.y);
        __half2 h1 = __floats2half2_rn(v.z, v.w);
        o.x = *(uint32_t*)&h0; o.y = *(uint32_t*)&h1;
    }
    *(uint2*)(g_Ah + (size_t)row * 512 + col) = o;
}

// W [K=512][N] f32 -> Bt [N][1024] fp16 ([Bh|Bl]), N-major rows
__global__ void convert_B_kernel(const float* __restrict__ W, __half* __restrict__ Bt, int N) {
    int idx = blockIdx.x * 256 + threadIdx.x;
    if (idx >= 512 * N) return;
    int k = idx / N, n = idx % N;
    float v = W[idx];
    __half hi = __float2half_rn(v);
    float l = v - __half2float(hi);
    Bt[(size_t)n * 1024 + k] = hi;
    Bt[(size_t)n * 1024 + 512 + k] = __float2half_rn(l);
}

// heads weights -> g_Whd [128 rows][512] fp16 split ([hi 256|lo 256]); rows >= 72 zero. + g_ball
__global__ void pack_heads_kernel(
    const float* __restrict__ We, const float* __restrict__ be,
    const float* __restrict__ Wh, const float* __restrict__ bh,
    const float* __restrict__ Wg, const float* __restrict__ bg) {
    int idx = blockIdx.x * blockDim.x + threadIdx.x;
    if (idx < 128 * 256) {
        int n = idx >> 8, k = idx & 255;
        float v = 0.f;
        if (n < 7) v = We[k * 7 + n];
        else if (n < 15) v = Wh[k * 8 + (n - 7)];
        else if (n < 72) v = Wg[k * 57 + (n - 15)];
        __half hi = __float2half_rn(v);
        float l = v - __half2float(hi);
        g_Whd[n * 512 + k] = hi;
        g_Whd[n * 512 + 256 + k] = __float2half_rn(l);
    }
    if (idx < 72) {
        float v;
        if (idx < 7) v = be[idx];
        else if (idx < 15) v = bh[idx - 7];
        else v = bg[idx - 15];
        g_ball[idx] = v;
    }
}

// ---------------- mma.sync GEMM: C[M,N] = A @ (Bh+Bl)^T (fp16, fp32 accum) ----
// A: [M, TERMK] fp16 (exact). B: [N, 2*TERMK] fp16 split. 2*TERMK/32 K-stages of 32.
// CTA 128x128, 8 warps of 64x32. 4-stage cp.async pipeline.
#define SROW 40
#define STG_BYTES (128 * SROW * 2)   // 10240 B per tile per stage
template <int TERMK, typename OutT>
__global__ __launch_bounds__(256) void gemm_mma_kernel(
    const __half* __restrict__ A, const __half* __restrict__ Bt,
    OutT* __restrict__ C, int M, int N)
{
    extern __shared__ __align__(16) __half dsmem[];
    const uint32_t as_u32 = smem_u32(dsmem);
    const uint32_t bs_u32 = as_u32 + 4 * STG_BYTES;

    constexpr int NSTG = 2 * TERMK / 32;
    constexpr int TPS = TERMK / 32;   // stages per term
    constexpr int BRS = 2 * TERMK;    // B row stride (elems)

    const int tid = threadIdx.x;
    const int wid = tid >> 5, lane = tid & 31;
    const int bm = blockIdx.y * 128;
    const int bn = blockIdx.x * 128;
    const int warp_m = (wid >> 2) * 64;
    const int warp_n = (wid & 3) * 32;

    const int lrow = tid >> 2;
    const int lseg = (tid & 3) << 3;

    auto gload_async = [&](int s) {
        int term = s / TPS, kk = (s % TPS) << 5;
        int bc = term * TERMK + kk;            // B terms: Bh, Bl
        uint32_t ab = as_u32 + (uint32_t)(s & 3) * STG_BYTES;
        uint32_t bb = bs_u32 + (uint32_t)(s & 3) * STG_BYTES;
        #pragma unroll
        for (int i = 0; i < 2; ++i) {
            int row = lrow + i * 64;
            const __half* pa = A + (size_t)(bm + row) * TERMK + kk + lseg;
            const __half* pb = Bt + (size_t)(bn + row) * BRS + bc + lseg;
            uint32_t off = (uint32_t)(row * SROW + lseg) * 2;
            CP_ASYNC16(ab + off, pa);
            CP_ASYNC16(bb + off, pb);
        }
    };

    float acc[4][4][4];
    #pragma unroll
    for (int mi = 0; mi < 4; mi++)
        #pragma unroll
        for (int ni = 0; ni < 4; ni++)
            #pragma unroll
            for (int j = 0; j < 4; j++) acc[mi][ni][j] = 0.f;

    const uint32_t a_lm = as_u32 + (uint32_t)(warp_m + (lane & 15)) * (SROW * 2) + ((lane >> 4) << 4);
    const int bq = lane >> 3;
    const uint32_t b_lm = bs_u32 + (uint32_t)(warp_n + ((bq >> 1) << 3) + (lane & 7)) * (SROW * 2)
                          + ((bq & 1) << 4);

    auto compute = [&](int bi) {
        uint32_t soff = (uint32_t)bi * STG_BYTES;
        #pragma unroll
        for (int ks = 0; ks < 2; ++ks) {
            uint32_t a[4][4], b[4][2];
            #pragma unroll
            for (int mi = 0; mi < 4; mi++)
                ldsm4(a[mi], a_lm + soff + (uint32_t)mi * 16 * (SROW * 2) + ks * 32);
            #pragma unroll
            for (int nb = 0; nb < 2; nb++) {
                uint32_t r[4];
                ldsm4(r, b_lm + soff + (uint32_t)nb * 16 * (SROW * 2) + ks * 32);
                b[nb * 2][0] = r[0]; b[nb * 2][1] = r[1];
                b[nb * 2 + 1][0] = r[2]; b[nb * 2 + 1][1] = r[3];
            }
            #pragma unroll
            for (int mi = 0; mi < 4; mi++)
                #pragma unroll
                for (int ni = 0; ni < 4; ni++)
                    mma16816(acc[mi][ni], a[mi], b[ni]);
        }
    };

    gload_async(0); CP_COMMIT();
    gload_async(1); CP_COMMIT();
    gload_async(2); CP_COMMIT();

    for (int s = 0; s < NSTG; ++s) {
        CP_WAIT2();
        __syncthreads();
        if (s + 3 < NSTG) gload_async(s + 3);
        CP_COMMIT();
        compute(s & 3);
    }

    #pragma unroll
    for (int mi = 0; mi < 4; mi++) {
        int row0 = bm + warp_m + mi * 16 + (lane >> 2);
        #pragma unroll
        for (int ni = 0; ni < 4; ni++) {
            int col = bn + warp_n + ni * 8 + ((lane & 3) << 1);
            #pragma unroll
            for (int half_ = 0; half_ < 2; ++half_) {
                int r = row0 + half_ * 8;
                if (r < M) {
                    float v0 = acc[mi][ni][half_ * 2 + 0];
                    float v1 = acc[mi][ni][half_ * 2 + 1];
                    if (sizeof(OutT) == 4) {
                        *(float2*)&(((float*)C)[(size_t)r * N + col]) = make_float2(v0, v1);
                    } else {
                        __half2 h = __floats2half2_rn(v0, v1);
                        *(__half2*)&(((__half*)C)[(size_t)r * N + col]) = h;
                    }
                }
            }
        }
    }
}

// ---------------- aggregation (hidden layers, fp16 gather, D=512) ----------------
// h = relu(bias + dis^2*Y[i] + sum val*Y[col]); writes fp16 into g_Ah.
__global__ __launch_bounds__(256) void aggregate_h_kernel(
    const __half* __restrict__ Y, const float* __restrict__ bias) {
    int gt = blockIdx.x * 256 + threadIdx.x;
    int node = gt >> 6;          // 64 threads/node
    int lane = gt & 63;
    if (node >= NN) return;
    int c = lane << 3;           // 8 elems/thread

    float acc[8];
    float dv = g_dis[node];
    float w = dv * dv;
    {
        float4 b0 = *(const float4*)(bias + c);
        float4 b1 = *(const float4*)(bias + c + 4);
        uint4 raw = *(const uint4*)(Y + (size_t)node * 512 + c);
        const __half2* h = (const __half2*)&raw;
        float2 f0 = __half22float2(h[0]), f1 = __half22float2(h[1]);
        float2 f2 = __half22float2(h[2]), f3 = __half22float2(h[3]);
        acc[0] = fmaf(w, f0.x, b0.x); acc[1] = fmaf(w, f0.y, b0.y);
        acc[2] = fmaf(w, f1.x, b0.z); acc[3] = fmaf(w, f1.y, b0.w);
        acc[4] = fmaf(w, f2.x, b1.x); acc[5] = fmaf(w, f2.y, b1.y);
        acc[6] = fmaf(w, f3.x, b1.z); acc[7] = fmaf(w, f3.y, b1.w);
    }

    int e0 = g_rowptr[node], e1 = g_rowptr[node + 1];
    int p = e0;
    for (; p + 2 <= e1; p += 2) {
        int2 cv0 = __ldg(&g_colval[p + 0]);
        int2 cv1 = __ldg(&g_colval[p + 1]);
        uint4 r0 = *(const uint4*)(Y + (size_t)cv0.x * 512 + c);
        uint4 r1 = *(const uint4*)(Y + (size_t)cv1.x * 512 + c);
        float v0 = __int_as_float(cv0.y), v1 = __int_as_float(cv1.y);
        const __half2* h0 = (const __half2*)&r0;
        const __half2* h1 = (const __half2*)&r1;
        #pragma unroll
        for (int q = 0; q < 4; ++q) {
            float2 f0 = __half22float2(h0[q]);
            float2 f1 = __half22float2(h1[q]);
            acc[q * 2 + 0] = fmaf(v0, f0.x, acc[q * 2 + 0]);
            acc[q * 2 + 1] = fmaf(v0, f0.y, acc[q * 2 + 1]);
            acc[q * 2 + 0] = fmaf(v1, f1.x, acc[q * 2 + 0]);
            acc[q * 2 + 1] = fmaf(v1, f1.y, acc[q * 2 + 1]);
        }
    }
    for (; p < e1; ++p) {
        int2 cv = __ldg(&g_colval[p]);
        float v = __int_as_float(cv.y);
        uint4 r = *(const uint4*)(Y + (size_t)cv.x * 512 + c);
        const __half2* h = (const __half2*)&r;
        #pragma unroll
        for (int q = 0; q < 4; ++q) {
            float2 f = __half22float2(h[q]);
            acc[q * 2 + 0] = fmaf(v, f.x, acc[q * 2 + 0]);
            acc[q * 2 + 1] = fmaf(v, f.y, acc[q * 2 + 1]);
        }
    }
    uint4 o;
    __half2 h0 = __floats2half2_rn(fmaxf(acc[0], 0.f), fmaxf(acc[1], 0.f));
    __half2 h1 = __floats2half2_rn(fmaxf(acc[2], 0.f), fmaxf(acc[3], 0.f));
    __half2 h2 = __floats2half2_rn(fmaxf(acc[4], 0.f), fmaxf(acc[5], 0.f));
    __half2 h3 = __floats2half2_rn(fmaxf(acc[6], 0.f), fmaxf(acc[7], 0.f));
    o.x = *(uint32_t*)&h0; o.y = *(uint32_t*)&h1;
    o.z = *(uint32_t*)&h2; o.w = *(uint32_t*)&h3;
    *(uint4*)(g_Ah + (size_t)node * 512 + c) = o;
}

// ---------------- layer-3 aggregation (fp16 gather, D=256) -> emb f32 + heads fp16 ----------------
__global__ __launch_bounds__(256) void aggregate3_kernel(
    const __half* __restrict__ Y, float* __restrict__ emb, const float* __restrict__ bias,
    __half* __restrict__ Ahd) {
    int gt = blockIdx.x * 256 + threadIdx.x;
    int node = gt >> 5;          // 32 threads/node
    int lane = gt & 31;
    if (node >= MPAD) return;
    int c = lane << 3;           // 8 elems/thread
    if (node >= NN) {            // zero heads-A padding rows
        *(uint4*)(Ahd + (size_t)node * 256 + c) = make_uint4(0, 0, 0, 0);
        return;
    }

    float acc[8];
    float dv = g_dis[node];
    float w = dv * dv;
    {
        float4 b0 = *(const float4*)(bias + c);
        float4 b1 = *(const float4*)(bias + c + 4);
        uint4 raw = *(const uint4*)(Y + (size_t)node * 256 + c);
        const __half2* h = (const __half2*)&raw;
        float2 f0 = __half22float2(h[0]), f1 = __half22float2(h[1]);
        float2 f2 = __half22float2(h[2]), f3 = __half22float2(h[3]);
        acc[0] = fmaf(w, f0.x, b0.x); acc[1] = fmaf(w, f0.y, b0.y);
        acc[2] = fmaf(w, f1.x, b0.z); acc[3] = fmaf(w, f1.y, b0.w);
        acc[4] = fmaf(w, f2.x, b1.x); acc[5] = fmaf(w, f2.y, b1.y);
        acc[6] = fmaf(w, f3.x, b1.z); acc[7] = fmaf(w, f3.y, b1.w);
    }

    int e0 = g_rowptr[node], e1 = g_rowptr[node + 1];
    for (int p = e0; p < e1; ++p) {
        int2 cv = __ldg(&g_colval[p]);
        float v = __int_as_float(cv.y);
        uint4 r = *(const uint4*)(Y + (size_t)cv.x * 256 + c);
        const __half2* h = (const __half2*)&r;
        #pragma unroll
        for (int q = 0; q < 4; ++q) {
            float2 f = __half22float2(h[q]);
            acc[q * 2 + 0] = fmaf(v, f.x, acc[q * 2 + 0]);
            acc[q * 2 + 1] = fmaf(v, f.y, acc[q * 2 + 1]);
        }
    }
    *(float4*)(emb + (size_t)node * 256 + c) =
        make_float4(acc[0], acc[1], acc[2], acc[3]);
    *(float4*)(emb + (size_t)node * 256 + c + 4) =
        make_float4(acc[4], acc[5], acc[6], acc[7]);
    uint4 o;
    __half2 h0 = __floats2half2_rn(acc[0], acc[1]);
    __half2 h1 = __floats2half2_rn(acc[2], acc[3]);
    __half2 h2 = __floats2half2_rn(acc[4], acc[5]);
    __half2 h3 = __floats2half2_rn(acc[6], acc[7]);
    o.x = *(uint32_t*)&h0; o.y = *(uint32_t*)&h1;
    o.z = *(uint32_t*)&h2; o.w = *(uint32_t*)&h3;
    *(uint4*)(Ahd + (size_t)node * 256 + c) = o;
}

// ---------------- head output split (adds bias) ----------------
__global__ void split_heads_kernel(const float* __restrict__ T,
                                   float* __restrict__ outE,
                                   float* __restrict__ outH,
                                   float* __restrict__ outG) {
    int idx = blockIdx.x * blockDim.x + threadIdx.x;
    if (idx >= NN * 72) return;
    int i = idx / 72, j = idx % 72;
    float v = T[(size_t)i * 128 + j] + g_ball[j];
    if (j < 7) outE[i * 7 + j] = v;
    else if (j < 15) outH[i * 8 + (j - 7)] = v;
    else outG[i * 57 + (j - 15)] = v;
}

// ---------------- launch ----------------
extern "C" void kernel_launch(void* const* d_in, const int* in_sizes, int n_in,
                              void* d_out, int out_size) {
    const float* x  = (const float*)d_in[0];
    const int*   ei = (const int*)d_in[1];
    const float* W1 = (const float*)d_in[2];
    const float* b1 = (const float*)d_in[3];
    const float* W2 = (const float*)d_in[4];
    const float* b2 = (const float*)d_in[5];
    const float* W3 = (const float*)d_in[6];
    const float* b3 = (const float*)d_in[7];
    const float* We = (const float*)d_in[8];
    const float* be = (const float*)d_in[9];
    const float* Wh = (const float*)d_in[10];
    const float* bh = (const float*)d_in[11];
    const float* Wg = (const float*)d_in[12];
    const float* bg = (const float*)d_in[13];

    const int* srcArr = ei;
    const int* dstArr = ei + NE;

    float* out  = (float*)d_out;
    float* emb  = out;
    float* outE = out + (size_t)NN * 256;
    float* outH = outE + (size_t)NN * 7;
    float* outG = outH + (size_t)NN * 8;

    float *buf1, *buf2;
    __half *Ah, *Bt1, *Bt2, *Bt3, *Whd;
    cudaGetSymbolAddress((void**)&buf1, g_buf1);
    cudaGetSymbolAddress((void**)&buf2, g_buf2);
    cudaGetSymbolAddress((void**)&Ah,  g_Ah);
    cudaGetSymbolAddress((void**)&Bt1, g_Bt1);
    cudaGetSymbolAddress((void**)&Bt2, g_Bt2);
    cudaGetSymbolAddress((void**)&Bt3, g_Bt3);
    cudaGetSymbolAddress((void**)&Whd, g_Whd);

    const int GEMM_SMEM = 8 * STG_BYTES;  // 81920 B
    cudaFuncSetAttribute(gemm_mma_kernel<512, __half>, cudaFuncAttributeMaxDynamicSharedMemorySize, GEMM_SMEM);
    cudaFuncSetAttribute(gemm_mma_kernel<256, float>,  cudaFuncAttributeMaxDynamicSharedMemorySize, GEMM_SMEM);

    // weight conversions (independent of CSR)
    convert_B_kernel<<<(512 * 512 + 255) / 256, 256>>>(W1, Bt1, 512);
    convert_B_kernel<<<(512 * 512 + 255) / 256, 256>>>(W2, Bt2, 512);
    convert_B_kernel<<<(512 * 256 + 255) / 256, 256>>>(W3, Bt3, 256);
    pack_heads_kernel<<<(128 * 256 + 255) / 256, 256>>>(We, be, Wh, bh, Wg, bg);

    // CSR build
    zero_indeg_kernel<<<(NN + 255) / 256, 256>>>();
    count_kernel<<<(NE + 255) / 256, 256>>>(dstArr);
    dis_kernel<<<(NN + 255) / 256, 256>>>();
    scan_part1<<<49, 1024>>>();
    scan_part2<<<1, 1>>>();
    scan_part3<<<49, 1024>>>();
    scatter_kernel<<<(NE + 255) / 256, 256>>>(srcArr, dstArr);

    const int gm = MPAD / 128;  // 391
    __half* bufh = (__half*)buf1;
    __half* Ahd = (__half*)buf2;

    // layer 1
    convert_x_kernel<<<(MPAD * 128 + 255) / 256, 256>>>(x);
    gemm_mma_kernel<512, __half><<<dim3(4, gm), 256, GEMM_SMEM>>>(Ah, Bt1, bufh, NN, 512);
    aggregate_h_kernel<<<NN / 4, 256>>>(bufh, b1);   // -> g_Ah (fp16)
    // layer 2
    gemm_mma_kernel<512, __half><<<dim3(4, gm), 256, GEMM_SMEM>>>(Ah, Bt2, bufh, NN, 512);
    aggregate_h_kernel<<<NN / 4, 256>>>(bufh, b2);   // -> g_Ah (fp16)
    // layer 3 (fp16 Y, emb f32 output + heads fp16 A)
    gemm_mma_kernel<512, __half><<<dim3(2, gm), 256, GEMM_SMEM>>>(Ah, Bt3, bufh, NN, 256);
    aggregate3_kernel<<<MPAD / 8, 256>>>(bufh, emb, b3, Ahd);
    // heads: [NN,256] fp16 @ Whd[128, 512 split] -> buf1 f32 [NN,128]
    gemm_mma_kernel<256, float><<<dim3(1, gm), 256, GEMM_SMEM>>>(Ahd, Whd, buf1, NN, 128);
    split_heads_kernel<<<(NN * 72 + 255) / 256, 256>>>(buf1, outE, outH, outG);
}

// round 12
// speedup vs baseline: 2.2287x; 1.4038x over previous
#include <cuda_runtime.h>
#include <cuda_bf16.h>
#include <cuda_fp16.h>
#include <math.h>
#include <stdint.h>

#define NN 50000
#define NE 800000
#define MPAD 50048   // 391 * 128

// ---------------- device scratch (allocation-free) ----------------
__device__ float g_buf1[NN * 512];          // GEMM output buffer (f32 / fp16 alias)
__device__ float g_buf2[NN * 512];          // heads A (fp16 alias) / spare
__device__ __half g_Ah[(size_t)MPAD * 512]; // fp16 activations (GEMM A operand)
__device__ __half g_Bt1[512 * 512];         // fp16 weights, N-major rows, K-contig
__device__ __half g_Bt2[512 * 512];
__device__ __half g_Bt3[256 * 512];
__device__ __half g_Whd[128 * 512];         // heads B: [hi 256 | lo 256], rows>=72 zero
__device__ float g_dis[NN];
__device__ int   g_indeg[NN];
__device__ int   g_rowptr[NN + 1];
__device__ int   g_cursor[NN];
__device__ int2  g_colval[NE];              // (col, val bits)
__device__ float g_ball[72];
__device__ int   g_blocksum[64];

// ---------------- helpers ----------------
__device__ __forceinline__ uint32_t smem_u32(const void* p) {
    uint32_t a;
    asm("{ .reg .u64 t; cvta.to.shared.u64 t, %1; cvt.u32.u64 %0, t; }" : "=r"(a) : "l"(p));
    return a;
}
__device__ __forceinline__ void ldsm4(uint32_t* r, uint32_t addr) {
    asm volatile("ldmatrix.sync.aligned.m8n8.x4.shared.b16 {%0,%1,%2,%3}, [%4];"
                 : "=r"(r[0]), "=r"(r[1]), "=r"(r[2]), "=r"(r[3]) : "r"(addr));
}
__device__ __forceinline__ void mma16816(float* c, const uint32_t* a, const uint32_t* b) {
    asm volatile("mma.sync.aligned.m16n8k16.row.col.f32.f16.f16.f32 "
                 "{%0,%1,%2,%3}, {%4,%5,%6,%7}, {%8,%9}, {%0,%1,%2,%3};"
                 : "+f"(c[0]), "+f"(c[1]), "+f"(c[2]), "+f"(c[3])
                 : "r"(a[0]), "r"(a[1]), "r"(a[2]), "r"(a[3]), "r"(b[0]), "r"(b[1]));
}
#define CP_ASYNC16(dst, src) \
    asm volatile("cp.async.cg.shared.global [%0], [%1], 16;" :: "r"(dst), "l"(src))
#define CP_COMMIT() asm volatile("cp.async.commit_group;" ::: "memory")
#define CP_WAIT2()  asm volatile("cp.async.wait_group 2;" ::: "memory")

// ---------------- CSR build ----------------
__global__ void zero_indeg_kernel() {
    int i = blockIdx.x * blockDim.x + threadIdx.x;
    if (i < NN) g_indeg[i] = 0;
}
__global__ void count_kernel(const int* __restrict__ dst) {
    int e = blockIdx.x * blockDim.x + threadIdx.x;
    if (e < NE) atomicAdd(&g_indeg[dst[e]], 1);
}
__global__ void dis_kernel() {
    int i = blockIdx.x * blockDim.x + threadIdx.x;
    if (i < NN) g_dis[i] = rsqrtf((float)(g_indeg[i] + 1));
}
__global__ void scan_part1() {
    __shared__ int ws[32];
    int i = blockIdx.x * 1024 + threadIdx.x;
    int v = (i < NN) ? g_indeg[i] : 0;
    #pragma unroll
    for (int o = 16; o > 0; o >>= 1) v += __shfl_down_sync(0xffffffffu, v, o);
    if ((threadIdx.x & 31) == 0) ws[threadIdx.x >> 5] = v;
    __syncthreads();
    if (threadIdx.x < 32) {
        int s = ws[threadIdx.x];
        #pragma unroll
        for (int o = 16; o > 0; o >>= 1) s += __shfl_down_sync(0xffffffffu, s, o);
        if (threadIdx.x == 0) g_blocksum[blockIdx.x] = s;
    }
}
__global__ void scan_part2() {
    int acc = 0;
    for (int b = 0; b < 49; ++b) { int t = g_blocksum[b]; g_blocksum[b] = acc; acc += t; }
    g_rowptr[NN] = acc;
}
__global__ void scan_part3() {
    __shared__ int ws[32];
    int tid = threadIdx.x;
    int i = blockIdx.x * 1024 + tid;
    int v = (i < NN) ? g_indeg[i] : 0;
    int x = v;
    #pragma unroll
    for (int o = 1; o < 32; o <<= 1) {
        int t = __shfl_up_sync(0xffffffffu, x, o);
        if ((tid & 31) >= o) x += t;
    }
    if ((tid & 31) == 31) ws[tid >> 5] = x;
    __syncthreads();
    if (tid < 32) {
        int s = ws[tid];
        #pragma unroll
        for (int o = 1; o < 32; o <<= 1) {
            int t = __shfl_up_sync(0xffffffffu, s, o);
            if (tid >= o) s += t;
        }
        ws[tid] = s;
    }
    __syncthreads();
    int wofs = (tid >= 32) ? ws[(tid >> 5) - 1] : 0;
    int excl = x + wofs - v + g_blocksum[blockIdx.x];
    if (i < NN) { g_rowptr[i] = excl; g_cursor[i] = excl; }
}
__global__ void scatter_kernel(const int* __restrict__ src, const int* __restrict__ dst) {
    int e = blockIdx.x * blockDim.x + threadIdx.x;
    if (e < NE) {
        int s = src[e], d = dst[e];
        int p = atomicAdd(&g_cursor[d], 1);
        g_colval[p] = make_int2(s, __float_as_int(g_dis[s] * g_dis[d]));
    }
}

// ---------------- conversions ----------------
// x f32 [NN,512] -> fp16 [MPAD,512], pad rows zero
__global__ void convert_x_kernel(const float* __restrict__ X) {
    int idx = blockIdx.x * 256 + threadIdx.x;
    if (idx >= MPAD * 128) return;
    int row = idx >> 7, col = (idx & 127) << 2;
    uint2 o = make_uint2(0, 0);
    if (row < NN) {
        float4 v = *(const float4*)(X + (size_t)row * 512 + col);
        __half2 h0 = __floats2half2_rn(v.x, v.y);
        __half2 h1 = __floats2half2_rn(v.z, v.w);
        o.x = *(uint32_t*)&h0; o.y = *(uint32_t*)&h1;
    }
    *(uint2*)(g_Ah + (size_t)row * 512 + col) = o;
}

// W [K=512][N] f32 -> Bt [N][512] fp16, N-major rows
__global__ void convert_B_kernel(const float* __restrict__ W, __half* __restrict__ Bt, int N) {
    int idx = blockIdx.x * 256 + threadIdx.x;
    if (idx >= 512 * N) return;
    int k = idx / N, n = idx % N;
    Bt[(size_t)n * 512 + k] = __float2half_rn(W[idx]);
}

// heads weights -> g_Whd [128 rows][512] fp16 split ([hi 256|lo 256]); rows >= 72 zero. + g_ball
__global__ void pack_heads_kernel(
    const float* __restrict__ We, const float* __restrict__ be,
    const float* __restrict__ Wh, const float* __restrict__ bh,
    const float* __restrict__ Wg, const float* __restrict__ bg) {
    int idx = blockIdx.x * blockDim.x + threadIdx.x;
    if (idx < 128 * 256) {
        int n = idx >> 8, k = idx & 255;
        float v = 0.f;
        if (n < 7) v = We[k * 7 + n];
        else if (n < 15) v = Wh[k * 8 + (n - 7)];
        else if (n < 72) v = Wg[k * 57 + (n - 15)];
        __half hi = __float2half_rn(v);
        float l = v - __half2float(hi);
        g_Whd[n * 512 + k] = hi;
        g_Whd[n * 512 + 256 + k] = __float2half_rn(l);
    }
    if (idx < 72) {
        float v;
        if (idx < 7) v = be[idx];
        else if (idx < 15) v = bh[idx - 7];
        else v = bg[idx - 15];
        g_ball[idx] = v;
    }
}

// ---------------- mma.sync GEMM: C[M,N] = A @ B^T (fp16, fp32 accum) ----
// A: [M, TERMK] fp16. B: [N, NTERMS*TERMK] fp16 (NTERMS=2 => residual split summed).
// NTERMS*TERMK/32 K-stages of 32. CTA 128x128, 8 warps of 64x32. 4-stage cp.async.
#define SROW 40
#define STG_BYTES (128 * SROW * 2)   // 10240 B per tile per stage
template <int TERMK, int NTERMS, typename OutT>
__global__ __launch_bounds__(256) void gemm_mma_kernel(
    const __half* __restrict__ A, const __half* __restrict__ Bt,
    OutT* __restrict__ C, int M, int N)
{
    extern __shared__ __align__(16) __half dsmem[];
    const uint32_t as_u32 = smem_u32(dsmem);
    const uint32_t bs_u32 = as_u32 + 4 * STG_BYTES;

    constexpr int NSTG = NTERMS * TERMK / 32;
    constexpr int TPS = TERMK / 32;      // stages per term
    constexpr int BRS = NTERMS * TERMK;  // B row stride (elems)

    const int tid = threadIdx.x;
    const int wid = tid >> 5, lane = tid & 31;
    const int bm = blockIdx.y * 128;
    const int bn = blockIdx.x * 128;
    const int warp_m = (wid >> 2) * 64;
    const int warp_n = (wid & 3) * 32;

    const int lrow = tid >> 2;
    const int lseg = (tid & 3) << 3;

    auto gload_async = [&](int s) {
        int term = s / TPS, kk = (s % TPS) << 5;
        int bc = term * TERMK + kk;
        uint32_t ab = as_u32 + (uint32_t)(s & 3) * STG_BYTES;
        uint32_t bb = bs_u32 + (uint32_t)(s & 3) * STG_BYTES;
        #pragma unroll
        for (int i = 0; i < 2; ++i) {
            int row = lrow + i * 64;
            const __half* pa = A + (size_t)(bm + row) * TERMK + kk + lseg;
            const __half* pb = Bt + (size_t)(bn + row) * BRS + bc + lseg;
            uint32_t off = (uint32_t)(row * SROW + lseg) * 2;
            CP_ASYNC16(ab + off, pa);
            CP_ASYNC16(bb + off, pb);
        }
    };

    float acc[4][4][4];
    #pragma unroll
    for (int mi = 0; mi < 4; mi++)
        #pragma unroll
        for (int ni = 0; ni < 4; ni++)
            #pragma unroll
            for (int j = 0; j < 4; j++) acc[mi][ni][j] = 0.f;

    const uint32_t a_lm = as_u32 + (uint32_t)(warp_m + (lane & 15)) * (SROW * 2) + ((lane >> 4) << 4);
    const int bq = lane >> 3;
    const uint32_t b_lm = bs_u32 + (uint32_t)(warp_n + ((bq >> 1) << 3) + (lane & 7)) * (SROW * 2)
                          + ((bq & 1) << 4);

    auto compute = [&](int bi) {
        uint32_t soff = (uint32_t)bi * STG_BYTES;
        #pragma unroll
        for (int ks = 0; ks < 2; ++ks) {
            uint32_t a[4][4], b[4][2];
            #pragma unroll
            for (int mi = 0; mi < 4; mi++)
                ldsm4(a[mi], a_lm + soff + (uint32_t)mi * 16 * (SROW * 2) + ks * 32);
            #pragma unroll
            for (int nb = 0; nb < 2; nb++) {
                uint32_t r[4];
                ldsm4(r, b_lm + soff + (uint32_t)nb * 16 * (SROW * 2) + ks * 32);
                b[nb * 2][0] = r[0]; b[nb * 2][1] = r[1];
                b[nb * 2 + 1][0] = r[2]; b[nb * 2 + 1][1] = r[3];
            }
            #pragma unroll
            for (int mi = 0; mi < 4; mi++)
                #pragma unroll
                for (int ni = 0; ni < 4; ni++)
                    mma16816(acc[mi][ni], a[mi], b[ni]);
        }
    };

    gload_async(0); CP_COMMIT();
    gload_async(1); CP_COMMIT();
    gload_async(2); CP_COMMIT();

    for (int s = 0; s < NSTG; ++s) {
        CP_WAIT2();
        __syncthreads();
        if (s + 3 < NSTG) gload_async(s + 3);
        CP_COMMIT();
        compute(s & 3);
    }

    #pragma unroll
    for (int mi = 0; mi < 4; mi++) {
        int row0 = bm + warp_m + mi * 16 + (lane >> 2);
        #pragma unroll
        for (int ni = 0; ni < 4; ni++) {
            int col = bn + warp_n + ni * 8 + ((lane & 3) << 1);
            #pragma unroll
            for (int half_ = 0; half_ < 2; ++half_) {
                int r = row0 + half_ * 8;
                if (r < M) {
                    float v0 = acc[mi][ni][half_ * 2 + 0];
                    float v1 = acc[mi][ni][half_ * 2 + 1];
                    if (sizeof(OutT) == 4) {
                        *(float2*)&(((float*)C)[(size_t)r * N + col]) = make_float2(v0, v1);
                    } else {
                        __half2 h = __floats2half2_rn(v0, v1);
                        *(__half2*)&(((__half*)C)[(size_t)r * N + col]) = h;
                    }
                }
            }
        }
    }
}

// ---------------- aggregation (hidden layers, fp16 gather, D=512) ----------------
// h = relu(bias + dis^2*Y[i] + sum val*Y[col]); writes fp16 into g_Ah.
__global__ __launch_bounds__(256) void aggregate_h_kernel(
    const __half* __restrict__ Y, const float* __restrict__ bias) {
    int gt = blockIdx.x * 256 + threadIdx.x;
    int node = gt >> 6;          // 64 threads/node
    int lane = gt & 63;
    if (node >= NN) return;
    int c = lane << 3;           // 8 elems/thread

    float acc[8];
    float dv = g_dis[node];
    float w = dv * dv;
    {
        float4 b0 = *(const float4*)(bias + c);
        float4 b1 = *(const float4*)(bias + c + 4);
        uint4 raw = *(const uint4*)(Y + (size_t)node * 512 + c);
        const __half2* h = (const __half2*)&raw;
        float2 f0 = __half22float2(h[0]), f1 = __half22float2(h[1]);
        float2 f2 = __half22float2(h[2]), f3 = __half22float2(h[3]);
        acc[0] = fmaf(w, f0.x, b0.x); acc[1] = fmaf(w, f0.y, b0.y);
        acc[2] = fmaf(w, f1.x, b0.z); acc[3] = fmaf(w, f1.y, b0.w);
        acc[4] = fmaf(w, f2.x, b1.x); acc[5] = fmaf(w, f2.y, b1.y);
        acc[6] = fmaf(w, f3.x, b1.z); acc[7] = fmaf(w, f3.y, b1.w);
    }

    int e0 = g_rowptr[node], e1 = g_rowptr[node + 1];
    int p = e0;
    for (; p + 2 <= e1; p += 2) {
        int2 cv0 = __ldg(&g_colval[p + 0]);
        int2 cv1 = __ldg(&g_colval[p + 1]);
        uint4 r0 = *(const uint4*)(Y + (size_t)cv0.x * 512 + c);
        uint4 r1 = *(const uint4*)(Y + (size_t)cv1.x * 512 + c);
        float v0 = __int_as_float(cv0.y), v1 = __int_as_float(cv1.y);
        const __half2* h0 = (const __half2*)&r0;
        const __half2* h1 = (const __half2*)&r1;
        #pragma unroll
        for (int q = 0; q < 4; ++q) {
            float2 f0 = __half22float2(h0[q]);
            float2 f1 = __half22float2(h1[q]);
            acc[q * 2 + 0] = fmaf(v0, f0.x, acc[q * 2 + 0]);
            acc[q * 2 + 1] = fmaf(v0, f0.y, acc[q * 2 + 1]);
            acc[q * 2 + 0] = fmaf(v1, f1.x, acc[q * 2 + 0]);
            acc[q * 2 + 1] = fmaf(v1, f1.y, acc[q * 2 + 1]);
        }
    }
    for (; p < e1; ++p) {
        int2 cv = __ldg(&g_colval[p]);
        float v = __int_as_float(cv.y);
        uint4 r = *(const uint4*)(Y + (size_t)cv.x * 512 + c);
        const __half2* h = (const __half2*)&r;
        #pragma unroll
        for (int q = 0; q < 4; ++q) {
            float2 f = __half22float2(h[q]);
            acc[q * 2 + 0] = fmaf(v, f.x, acc[q * 2 + 0]);
            acc[q * 2 + 1] = fmaf(v, f.y, acc[q * 2 + 1]);
        }
    }
    uint4 o;
    __half2 h0 = __floats2half2_rn(fmaxf(acc[0], 0.f), fmaxf(acc[1], 0.f));
    __half2 h1 = __floats2half2_rn(fmaxf(acc[2], 0.f), fmaxf(acc[3], 0.f));
    __half2 h2 = __floats2half2_rn(fmaxf(acc[4], 0.f), fmaxf(acc[5], 0.f));
    __half2 h3 = __floats2half2_rn(fmaxf(acc[6], 0.f), fmaxf(acc[7], 0.f));
    o.x = *(uint32_t*)&h0; o.y = *(uint32_t*)&h1;
    o.z = *(uint32_t*)&h2; o.w = *(uint32_t*)&h3;
    *(uint4*)(g_Ah + (size_t)node * 512 + c) = o;
}

// ---------------- layer-3 aggregation (fp16 gather, D=256) -> emb f32 + heads fp16 ----------------
__global__ __launch_bounds__(256) void aggregate3_kernel(
    const __half* __restrict__ Y, float* __restrict__ emb, const float* __restrict__ bias,
    __half* __restrict__ Ahd) {
    int gt = blockIdx.x * 256 + threadIdx.x;
    int node = gt >> 5;          // 32 threads/node
    int lane = gt & 31;
    if (node >= MPAD) return;
    int c = lane << 3;           // 8 elems/thread
    if (node >= NN) {            // zero heads-A padding rows
        *(uint4*)(Ahd + (size_t)node * 256 + c) = make_uint4(0, 0, 0, 0);
        return;
    }

    float acc[8];
    float dv = g_dis[node];
    float w = dv * dv;
    {
        float4 b0 = *(const float4*)(bias + c);
        float4 b1 = *(const float4*)(bias + c + 4);
        uint4 raw = *(const uint4*)(Y + (size_t)node * 256 + c);
        const __half2* h = (const __half2*)&raw;
        float2 f0 = __half22float2(h[0]), f1 = __half22float2(h[1]);
        float2 f2 = __half22float2(h[2]), f3 = __half22float2(h[3]);
        acc[0] = fmaf(w, f0.x, b0.x); acc[1] = fmaf(w, f0.y, b0.y);
        acc[2] = fmaf(w, f1.x, b0.z); acc[3] = fmaf(w, f1.y, b0.w);
        acc[4] = fmaf(w, f2.x, b1.x); acc[5] = fmaf(w, f2.y, b1.y);
        acc[6] = fmaf(w, f3.x, b1.z); acc[7] = fmaf(w, f3.y, b1.w);
    }

    int e0 = g_rowptr[node], e1 = g_rowptr[node + 1];
    for (int p = e0; p < e1; ++p) {
        int2 cv = __ldg(&g_colval[p]);
        float v = __int_as_float(cv.y);
        uint4 r = *(const uint4*)(Y + (size_t)cv.x * 256 + c);
        const __half2* h = (const __half2*)&r;
        #pragma unroll
        for (int q = 0; q < 4; ++q) {
            float2 f = __half22float2(h[q]);
            acc[q * 2 + 0] = fmaf(v, f.x, acc[q * 2 + 0]);
            acc[q * 2 + 1] = fmaf(v, f.y, acc[q * 2 + 1]);
        }
    }
    *(float4*)(emb + (size_t)node * 256 + c) =
        make_float4(acc[0], acc[1], acc[2], acc[3]);
    *(float4*)(emb + (size_t)node * 256 + c + 4) =
        make_float4(acc[4], acc[5], acc[6], acc[7]);
    uint4 o;
    __half2 h0 = __floats2half2_rn(acc[0], acc[1]);
    __half2 h1 = __floats2half2_rn(acc[2], acc[3]);
    __half2 h2 = __floats2half2_rn(acc[4], acc[5]);
    __half2 h3 = __floats2half2_rn(acc[6], acc[7]);
    o.x = *(uint32_t*)&h0; o.y = *(uint32_t*)&h1;
    o.z = *(uint32_t*)&h2; o.w = *(uint32_t*)&h3;
    *(uint4*)(Ahd + (size_t)node * 256 + c) = o;
}

// ---------------- head output split (adds bias) ----------------
__global__ void split_heads_kernel(const float* __restrict__ T,
                                   float* __restrict__ outE,
                                   float* __restrict__ outH,
                                   float* __restrict__ outG) {
    int idx = blockIdx.x * blockDim.x + threadIdx.x;
    if (idx >= NN * 72) return;
    int i = idx / 72, j = idx % 72;
    float v = T[(size_t)i * 128 + j] + g_ball[j];
    if (j < 7) outE[i * 7 + j] = v;
    else if (j < 15) outH[i * 8 + (j - 7)] = v;
    else outG[i * 57 + (j - 15)] = v;
}

// ---------------- launch ----------------
extern "C" void kernel_launch(void* const* d_in, const int* in_sizes, int n_in,
                              void* d_out, int out_size) {
    const float* x  = (const float*)d_in[0];
    const int*   ei = (const int*)d_in[1];
    const float* W1 = (const float*)d_in[2];
    const float* b1 = (const float*)d_in[3];
    const float* W2 = (const float*)d_in[4];
    const float* b2 = (const float*)d_in[5];
    const float* W3 = (const float*)d_in[6];
    const float* b3 = (const float*)d_in[7];
    const float* We = (const float*)d_in[8];
    const float* be = (const float*)d_in[9];
    const float* Wh = (const float*)d_in[10];
    const float* bh = (const float*)d_in[11];
    const float* Wg = (const float*)d_in[12];
    const float* bg = (const float*)d_in[13];

    const int* srcArr = ei;
    const int* dstArr = ei + NE;

    float* out  = (float*)d_out;
    float* emb  = out;
    float* outE = out + (size_t)NN * 256;
    float* outH = outE + (size_t)NN * 7;
    float* outG = outH + (size_t)NN * 8;

    float *buf1, *buf2;
    __half *Ah, *Bt1, *Bt2, *Bt3, *Whd;
    cudaGetSymbolAddress((void**)&buf1, g_buf1);
    cudaGetSymbolAddress((void**)&buf2, g_buf2);
    cudaGetSymbolAddress((void**)&Ah,  g_Ah);
    cudaGetSymbolAddress((void**)&Bt1, g_Bt1);
    cudaGetSymbolAddress((void**)&Bt2, g_Bt2);
    cudaGetSymbolAddress((void**)&Bt3, g_Bt3);
    cudaGetSymbolAddress((void**)&Whd, g_Whd);

    const int GEMM_SMEM = 8 * STG_BYTES;  // 81920 B
    cudaFuncSetAttribute(gemm_mma_kernel<512, 1, __half>, cudaFuncAttributeMaxDynamicSharedMemorySize, GEMM_SMEM);
    cudaFuncSetAttribute(gemm_mma_kernel<256, 2, float>,  cudaFuncAttributeMaxDynamicSharedMemorySize, GEMM_SMEM);

    // weight conversions (independent of CSR)
    convert_B_kernel<<<(512 * 512 + 255) / 256, 256>>>(W1, Bt1, 512);
    convert_B_kernel<<<(512 * 512 + 255) / 256, 256>>>(W2, Bt2, 512);
    convert_B_kernel<<<(512 * 256 + 255) / 256, 256>>>(W3, Bt3, 256);
    pack_heads_kernel<<<(128 * 256 + 255) / 256, 256>>>(We, be, Wh, bh, Wg, bg);

    // CSR build
    zero_indeg_kernel<<<(NN + 255) / 256, 256>>>();
    count_kernel<<<(NE + 255) / 256, 256>>>(dstArr);
    dis_kernel<<<(NN + 255) / 256, 256>>>();
    scan_part1<<<49, 1024>>>();
    scan_part2<<<1, 1>>>();
    scan_part3<<<49, 1024>>>();
    scatter_kernel<<<(NE + 255) / 256, 256>>>(srcArr, dstArr);

    const int gm = MPAD / 128;  // 391
    __half* bufh = (__half*)buf1;
    __half* Ahd = (__half*)buf2;

    // layer 1
    convert_x_kernel<<<(MPAD * 128 + 255) / 256, 256>>>(x);
    gemm_mma_kernel<512, 1, __half><<<dim3(4, gm), 256, GEMM_SMEM>>>(Ah, Bt1, bufh, NN, 512);
    aggregate_h_kernel<<<NN / 4, 256>>>(bufh, b1);   // -> g_Ah (fp16)
    // layer 2
    gemm_mma_kernel<512, 1, __half><<<dim3(4, gm), 256, GEMM_SMEM>>>(Ah, Bt2, bufh, NN, 512);
    aggregate_h_kernel<<<NN / 4, 256>>>(bufh, b2);   // -> g_Ah (fp16)
    // layer 3 (fp16 Y, emb f32 output + heads fp16 A)
    gemm_mma_kernel<512, 1, __half><<<dim3(2, gm), 256, GEMM_SMEM>>>(Ah, Bt3, bufh, NN, 256);
    aggregate3_kernel<<<MPAD / 8, 256>>>(bufh, emb, b3, Ahd);
    // heads: [NN,256] fp16 @ Whd[128, 512 split] -> buf1 f32 [NN,128]
    gemm_mma_kernel<256, 2, float><<<dim3(1, gm), 256, GEMM_SMEM>>>(Ahd, Whd, buf1, NN, 128);
    split_heads_kernel<<<(NN * 72 + 255) / 256, 256>>>(buf1, outE, outH, outG);
}

// round 15
// speedup vs baseline: 2.2653x; 1.0164x over previous
#include <cuda_runtime.h>
#include <cuda_bf16.h>
#include <cuda_fp16.h>
#include <math.h>
#include <stdint.h>

#define NN 50000
#define NE 800000
#define MPAD 50048   // 391 * 128

// ---------------- device scratch (allocation-free) ----------------
__device__ float g_buf1[NN * 512];          // GEMM output buffer (f32 / fp16 alias)
__device__ float g_buf2[NN * 512];          // heads A (fp16 alias) / spare
__device__ __half g_Ah[(size_t)MPAD * 512]; // fp16 activations (GEMM A operand)
__device__ __half g_Bt1[512 * 512];         // fp16 weights, N-major rows, K-contig
__device__ __half g_Bt2[512 * 512];
__device__ __half g_Bt3[256 * 512];
__device__ __half g_Whd[128 * 512];         // heads B: [hi 256 | lo 256], rows>=72 zero
__device__ float g_dis[NN];
__device__ int   g_indeg[NN];
__device__ int   g_rowptr[NN + 1];
__device__ int   g_cursor[NN];
__device__ int2  g_colval[NE];              // (col, val bits)
__device__ float g_ball[72];
__device__ int   g_blocksum[64];

// ---------------- helpers ----------------
__device__ __forceinline__ uint32_t smem_u32(const void* p) {
    uint32_t a;
    asm("{ .reg .u64 t; cvta.to.shared.u64 t, %1; cvt.u32.u64 %0, t; }" : "=r"(a) : "l"(p));
    return a;
}
__device__ __forceinline__ void ldsm4(uint32_t* r, uint32_t addr) {
    asm volatile("ldmatrix.sync.aligned.m8n8.x4.shared.b16 {%0,%1,%2,%3}, [%4];"
                 : "=r"(r[0]), "=r"(r[1]), "=r"(r[2]), "=r"(r[3]) : "r"(addr));
}
__device__ __forceinline__ void mma16816(float* c, const uint32_t* a, const uint32_t* b) {
    asm volatile("mma.sync.aligned.m16n8k16.row.col.f32.f16.f16.f32 "
                 "{%0,%1,%2,%3}, {%4,%5,%6,%7}, {%8,%9}, {%0,%1,%2,%3};"
                 : "+f"(c[0]), "+f"(c[1]), "+f"(c[2]), "+f"(c[3])
                 : "r"(a[0]), "r"(a[1]), "r"(a[2]), "r"(a[3]), "r"(b[0]), "r"(b[1]));
}
#define CP_ASYNC16(dst, src) \
    asm volatile("cp.async.cg.shared.global [%0], [%1], 16;" :: "r"(dst), "l"(src))
#define CP_COMMIT() asm volatile("cp.async.commit_group;" ::: "memory")
#define CP_WAIT2()  asm volatile("cp.async.wait_group 2;" ::: "memory")

// ---------------- CSR build ----------------
__global__ void zero_indeg_kernel() {
    int i = blockIdx.x * blockDim.x + threadIdx.x;
    if (i < NN) g_indeg[i] = 0;
}
__global__ void count_kernel(const int* __restrict__ dst) {
    int e = blockIdx.x * blockDim.x + threadIdx.x;
    if (e < NE) atomicAdd(&g_indeg[dst[e]], 1);
}
// block sums + fused dis computation
__global__ void scan_part1() {
    __shared__ int ws[32];
    int i = blockIdx.x * 1024 + threadIdx.x;
    int v = (i < NN) ? g_indeg[i] : 0;
    if (i < NN) g_dis[i] = rsqrtf((float)(v + 1));
    int s = v;
    #pragma unroll
    for (int o = 16; o > 0; o >>= 1) s += __shfl_down_sync(0xffffffffu, s, o);
    if ((threadIdx.x & 31) == 0) ws[threadIdx.x >> 5] = s;
    __syncthreads();
    if (threadIdx.x < 32) {
        int t = ws[threadIdx.x];
        #pragma unroll
        for (int o = 16; o > 0; o >>= 1) t += __shfl_down_sync(0xffffffffu, t, o);
        if (threadIdx.x == 0) g_blocksum[blockIdx.x] = t;
    }
}
__global__ void scan_part2() {
    int acc = 0;
    for (int b = 0; b < 49; ++b) { int t = g_blocksum[b]; g_blocksum[b] = acc; acc += t; }
    g_rowptr[NN] = acc;
}
__global__ void scan_part3() {
    __shared__ int ws[32];
    int tid = threadIdx.x;
    int i = blockIdx.x * 1024 + tid;
    int v = (i < NN) ? g_indeg[i] : 0;
    int x = v;
    #pragma unroll
    for (int o = 1; o < 32; o <<= 1) {
        int t = __shfl_up_sync(0xffffffffu, x, o);
        if ((tid & 31) >= o) x += t;
    }
    if ((tid & 31) == 31) ws[tid >> 5] = x;
    __syncthreads();
    if (tid < 32) {
        int s = ws[tid];
        #pragma unroll
        for (int o = 1; o < 32; o <<= 1) {
            int t = __shfl_up_sync(0xffffffffu, s, o);
            if (tid >= o) s += t;
        }
        ws[tid] = s;
    }
    __syncthreads();
    int wofs = (tid >= 32) ? ws[(tid >> 5) - 1] : 0;
    int excl = x + wofs - v + g_blocksum[blockIdx.x];
    if (i < NN) { g_rowptr[i] = excl; g_cursor[i] = excl; }
}
__global__ void scatter_kernel(const int* __restrict__ src, const int* __restrict__ dst) {
    int e = blockIdx.x * blockDim.x + threadIdx.x;
    if (e < NE) {
        int s = src[e], d = dst[e];
        int p = atomicAdd(&g_cursor[d], 1);
        g_colval[p] = make_int2(s, __float_as_int(g_dis[s] * g_dis[d]));
    }
}

// ---------------- conversions ----------------
// x f32 [NN,512] -> fp16 [MPAD,512], pad rows zero
__global__ void convert_x_kernel(const float* __restrict__ X) {
    int idx = blockIdx.x * 256 + threadIdx.x;
    if (idx >= MPAD * 128) return;
    int row = idx >> 7, col = (idx & 127) << 2;
    uint2 o = make_uint2(0, 0);
    if (row < NN) {
        float4 v = *(const float4*)(X + (size_t)row * 512 + col);
        __half2 h0 = __floats2half2_rn(v.x, v.y);
        __half2 h1 = __floats2half2_rn(v.z, v.w);
        o.x = *(uint32_t*)&h0; o.y = *(uint32_t*)&h1;
    }
    *(uint2*)(g_Ah + (size_t)row * 512 + col) = o;
}

// W [K=512][N] f32 -> Bt [N][512] fp16, N-major rows
__global__ void convert_B_kernel(const float* __restrict__ W, __half* __restrict__ Bt, int N) {
    int idx = blockIdx.x * 256 + threadIdx.x;
    if (idx >= 512 * N) return;
    int k = idx / N, n = idx % N;
    Bt[(size_t)n * 512 + k] = __float2half_rn(W[idx]);
}

// heads weights -> g_Whd [128 rows][512] fp16 split ([hi 256|lo 256]); rows >= 72 zero. + g_ball
__global__ void pack_heads_kernel(
    const float* __restrict__ We, const float* __restrict__ be,
    const float* __restrict__ Wh, const float* __restrict__ bh,
    const float* __restrict__ Wg, const float* __restrict__ bg) {
    int idx = blockIdx.x * blockDim.x + threadIdx.x;
    if (idx < 128 * 256) {
        int n = idx >> 8, k = idx & 255;
        float v = 0.f;
        if (n < 7) v = We[k * 7 + n];
        else if (n < 15) v = Wh[k * 8 + (n - 7)];
        else if (n < 72) v = Wg[k * 57 + (n - 15)];
        __half hi = __float2half_rn(v);
        float l = v - __half2float(hi);
        g_Whd[n * 512 + k] = hi;
        g_Whd[n * 512 + 256 + k] = __float2half_rn(l);
    }
    if (idx < 72) {
        float v;
        if (idx < 7) v = be[idx];
        else if (idx < 15) v = bh[idx - 7];
        else v = bg[idx - 15];
        g_ball[idx] = v;
    }
}

// ---------------- mma.sync GEMM: C[M,N] = A @ B^T (fp16, fp32 accum) ----
// A: [M, TERMK] fp16. B: [N, NTERMS*TERMK] fp16 (NTERMS=2 => residual split summed).
// NTERMS*TERMK/32 K-stages of 32. CTA 128x128, 8 warps of 64x32. 4-stage cp.async.
#define SROW 40
#define STG_BYTES (128 * SROW * 2)   // 10240 B per tile per stage
template <int TERMK, int NTERMS, typename OutT>
__global__ __launch_bounds__(256) void gemm_mma_kernel(
    const __half* __restrict__ A, const __half* __restrict__ Bt,
    OutT* __restrict__ C, int M, int N)
{
    extern __shared__ __align__(16) __half dsmem[];
    const uint32_t as_u32 = smem_u32(dsmem);
    const uint32_t bs_u32 = as_u32 + 4 * STG_BYTES;

    constexpr int NSTG = NTERMS * TERMK / 32;
    constexpr int TPS = TERMK / 32;      // stages per term
    constexpr int BRS = NTERMS * TERMK;  // B row stride (elems)

    const int tid = threadIdx.x;
    const int wid = tid >> 5, lane = tid & 31;
    const int bm = blockIdx.y * 128;
    const int bn = blockIdx.x * 128;
    const int warp_m = (wid >> 2) * 64;
    const int warp_n = (wid & 3) * 32;

    const int lrow = tid >> 2;
    const int lseg = (tid & 3) << 3;

    auto gload_async = [&](int s) {
        int term = s / TPS, kk = (s % TPS) << 5;
        int bc = term * TERMK + kk;
        uint32_t ab = as_u32 + (uint32_t)(s & 3) * STG_BYTES;
        uint32_t bb = bs_u32 + (uint32_t)(s & 3) * STG_BYTES;
        #pragma unroll
        for (int i = 0; i < 2; ++i) {
            int row = lrow + i * 64;
            const __half* pa = A + (size_t)(bm + row) * TERMK + kk + lseg;
            const __half* pb = Bt + (size_t)(bn + row) * BRS + bc + lseg;
            uint32_t off = (uint32_t)(row * SROW + lseg) * 2;
            CP_ASYNC16(ab + off, pa);
            CP_ASYNC16(bb + off, pb);
        }
    };

    float acc[4][4][4];
    #pragma unroll
    for (int mi = 0; mi < 4; mi++)
        #pragma unroll
        for (int ni = 0; ni < 4; ni++)
            #pragma unroll
            for (int j = 0; j < 4; j++) acc[mi][ni][j] = 0.f;

    const uint32_t a_lm = as_u32 + (uint32_t)(warp_m + (lane & 15)) * (SROW * 2) + ((lane >> 4) << 4);
    const int bq = lane >> 3;
    const uint32_t b_lm = bs_u32 + (uint32_t)(warp_n + ((bq >> 1) << 3) + (lane & 7)) * (SROW * 2)
                          + ((bq & 1) << 4);

    auto compute = [&](int bi) {
        uint32_t soff = (uint32_t)bi * STG_BYTES;
        #pragma unroll
        for (int ks = 0; ks < 2; ++ks) {
            uint32_t a[4][4], b[4][2];
            #pragma unroll
            for (int mi = 0; mi < 4; mi++)
                ldsm4(a[mi], a_lm + soff + (uint32_t)mi * 16 * (SROW * 2) + ks * 32);
            #pragma unroll
            for (int nb = 0; nb < 2; nb++) {
                uint32_t r[4];
                ldsm4(r, b_lm + soff + (uint32_t)nb * 16 * (SROW * 2) + ks * 32);
                b[nb * 2][0] = r[0]; b[nb * 2][1] = r[1];
                b[nb * 2 + 1][0] = r[2]; b[nb * 2 + 1][1] = r[3];
            }
            #pragma unroll
            for (int mi = 0; mi < 4; mi++)
                #pragma unroll
                for (int ni = 0; ni < 4; ni++)
                    mma16816(acc[mi][ni], a[mi], b[ni]);
        }
    };

    gload_async(0); CP_COMMIT();
    gload_async(1); CP_COMMIT();
    gload_async(2); CP_COMMIT();

    for (int s = 0; s < NSTG; ++s) {
        CP_WAIT2();
        __syncthreads();
        if (s + 3 < NSTG) gload_async(s + 3);
        CP_COMMIT();
        compute(s & 3);
    }

    #pragma unroll
    for (int mi = 0; mi < 4; mi++) {
        int row0 = bm + warp_m + mi * 16 + (lane >> 2);
        #pragma unroll
        for (int ni = 0; ni < 4; ni++) {
            int col = bn + warp_n + ni * 8 + ((lane & 3) << 1);
            #pragma unroll
            for (int half_ = 0; half_ < 2; ++half_) {
                int r = row0 + half_ * 8;
                if (r < M) {
                    float v0 = acc[mi][ni][half_ * 2 + 0];
                    float v1 = acc[mi][ni][half_ * 2 + 1];
                    if (sizeof(OutT) == 4) {
                        *(float2*)&(((float*)C)[(size_t)r * N + col]) = make_float2(v0, v1);
                    } else {
                        __half2 h = __floats2half2_rn(v0, v1);
                        *(__half2*)&(((__half*)C)[(size_t)r * N + col]) = h;
                    }
                }
            }
        }
    }
}

// ---------------- aggregation (hidden layers, fp16 gather, D=512) ----------------
__global__ __launch_bounds__(256) void aggregate_h_kernel(
    const __half* __restrict__ Y, const float* __restrict__ bias) {
    int gt = blockIdx.x * 256 + threadIdx.x;
    int node = gt >> 6;          // 64 threads/node
    int lane = gt & 63;
    if (node >= NN) return;
    int c = lane << 3;           // 8 elems/thread

    float acc[8];
    float dv = g_dis[node];
    float w = dv * dv;
    {
        float4 b0 = *(const float4*)(bias + c);
        float4 b1 = *(const float4*)(bias + c + 4);
        uint4 raw = *(const uint4*)(Y + (size_t)node * 512 + c);
        const __half2* h = (const __half2*)&raw;
        float2 f0 = __half22float2(h[0]), f1 = __half22float2(h[1]);
        float2 f2 = __half22float2(h[2]), f3 = __half22float2(h[3]);
        acc[0] = fmaf(w, f0.x, b0.x); acc[1] = fmaf(w, f0.y, b0.y);
        acc[2] = fmaf(w, f1.x, b0.z); acc[3] = fmaf(w, f1.y, b0.w);
        acc[4] = fmaf(w, f2.x, b1.x); acc[5] = fmaf(w, f2.y, b1.y);
        acc[6] = fmaf(w, f3.x, b1.z); acc[7] = fmaf(w, f3.y, b1.w);
    }

    int e0 = g_rowptr[node], e1 = g_rowptr[node + 1];
    int p = e0;
    for (; p + 2 <= e1; p += 2) {
        int2 cv0 = __ldg(&g_colval[p + 0]);
        int2 cv1 = __ldg(&g_colval[p + 1]);
        uint4 r0 = *(const uint4*)(Y + (size_t)cv0.x * 512 + c);
        uint4 r1 = *(const uint4*)(Y + (size_t)cv1.x * 512 + c);
        float v0 = __int_as_float(cv0.y), v1 = __int_as_float(cv1.y);
        const __half2* h0 = (const __half2*)&r0;
        const __half2* h1 = (const __half2*)&r1;
        #pragma unroll
        for (int q = 0; q < 4; ++q) {
            float2 f0 = __half22float2(h0[q]);
            float2 f1 = __half22float2(h1[q]);
            acc[q * 2 + 0] = fmaf(v0, f0.x, acc[q * 2 + 0]);
            acc[q * 2 + 1] = fmaf(v0, f0.y, acc[q * 2 + 1]);
            acc[q * 2 + 0] = fmaf(v1, f1.x, acc[q * 2 + 0]);
            acc[q * 2 + 1] = fmaf(v1, f1.y, acc[q * 2 + 1]);
        }
    }
    for (; p < e1; ++p) {
        int2 cv = __ldg(&g_colval[p]);
        float v = __int_as_float(cv.y);
        uint4 r = *(const uint4*)(Y + (size_t)cv.x * 512 + c);
        const __half2* h = (const __half2*)&r;
        #pragma unroll
        for (int q = 0; q < 4; ++q) {
            float2 f = __half22float2(h[q]);
            acc[q * 2 + 0] = fmaf(v, f.x, acc[q * 2 + 0]);
            acc[q * 2 + 1] = fmaf(v, f.y, acc[q * 2 + 1]);
        }
    }
    uint4 o;
    __half2 h0 = __floats2half2_rn(fmaxf(acc[0], 0.f), fmaxf(acc[1], 0.f));
    __half2 h1 = __floats2half2_rn(fmaxf(acc[2], 0.f), fmaxf(acc[3], 0.f));
    __half2 h2 = __floats2half2_rn(fmaxf(acc[4], 0.f), fmaxf(acc[5], 0.f));
    __half2 h3 = __floats2half2_rn(fmaxf(acc[6], 0.f), fmaxf(acc[7], 0.f));
    o.x = *(uint32_t*)&h0; o.y = *(uint32_t*)&h1;
    o.z = *(uint32_t*)&h2; o.w = *(uint32_t*)&h3;
    *(uint4*)(g_Ah + (size_t)node * 512 + c) = o;
}

// ---------------- layer-3 aggregation (fp16 gather, D=256) -> emb f32 + heads fp16 ----------------
__global__ __launch_bounds__(256) void aggregate3_kernel(
    const __half* __restrict__ Y, float* __restrict__ emb, const float* __restrict__ bias,
    __half* __restrict__ Ahd) {
    int gt = blockIdx.x * 256 + threadIdx.x;
    int node = gt >> 5;          // 32 threads/node
    int lane = gt & 31;
    if (node >= MPAD) return;
    int c = lane << 3;           // 8 elems/thread
    if (node >= NN) {            // zero heads-A padding rows
        *(uint4*)(Ahd + (size_t)node * 256 + c) = make_uint4(0, 0, 0, 0);
        return;
    }

    float acc[8];
    float dv = g_dis[node];
    float w = dv * dv;
    {
        float4 b0 = *(const float4*)(bias + c);
        float4 b1 = *(const float4*)(bias + c + 4);
        uint4 raw = *(const uint4*)(Y + (size_t)node * 256 + c);
        const __half2* h = (const __half2*)&raw;
        float2 f0 = __half22float2(h[0]), f1 = __half22float2(h[1]);
        float2 f2 = __half22float2(h[2]), f3 = __half22float2(h[3]);
        acc[0] = fmaf(w, f0.x, b0.x); acc[1] = fmaf(w, f0.y, b0.y);
        acc[2] = fmaf(w, f1.x, b0.z); acc[3] = fmaf(w, f1.y, b0.w);
        acc[4] = fmaf(w, f2.x, b1.x); acc[5] = fmaf(w, f2.y, b1.y);
        acc[6] = fmaf(w, f3.x, b1.z); acc[7] = fmaf(w, f3.y, b1.w);
    }

    int e0 = g_rowptr[node], e1 = g_rowptr[node + 1];
    for (int p = e0; p < e1; ++p) {
        int2 cv = __ldg(&g_colval[p]);
        float v = __int_as_float(cv.y);
        uint4 r = *(const uint4*)(Y + (size_t)cv.x * 256 + c);
        const __half2* h = (const __half2*)&r;
        #pragma unroll
        for (int q = 0; q < 4; ++q) {
            float2 f = __half22float2(h[q]);
            acc[q * 2 + 0] = fmaf(v, f.x, acc[q * 2 + 0]);
            acc[q * 2 + 1] = fmaf(v, f.y, acc[q * 2 + 1]);
        }
    }
    *(float4*)(emb + (size_t)node * 256 + c) =
        make_float4(acc[0], acc[1], acc[2], acc[3]);
    *(float4*)(emb + (size_t)node * 256 + c + 4) =
        make_float4(acc[4], acc[5], acc[6], acc[7]);
    uint4 o;
    __half2 h0 = __floats2half2_rn(acc[0], acc[1]);
    __half2 h1 = __floats2half2_rn(acc[2], acc[3]);
    __half2 h2 = __floats2half2_rn(acc[4], acc[5]);
    __half2 h3 = __floats2half2_rn(acc[6], acc[7]);
    o.x = *(uint32_t*)&h0; o.y = *(uint32_t*)&h1;
    o.z = *(uint32_t*)&h2; o.w = *(uint32_t*)&h3;
    *(uint4*)(Ahd + (size_t)node * 256 + c) = o;
}

// ---------------- head output split (adds bias) ----------------
__global__ void split_heads_kernel(const float* __restrict__ T,
                                   float* __restrict__ outE,
                                   float* __restrict__ outH,
                                   float* __restrict__ outG) {
    int idx = blockIdx.x * blockDim.x + threadIdx.x;
    if (idx >= NN * 72) return;
    int i = idx / 72, j = idx % 72;
    float v = T[(size_t)i * 128 + j] + g_ball[j];
    if (j < 7) outE[i * 7 + j] = v;
    else if (j < 15) outH[i * 8 + (j - 7)] = v;
    else outG[i * 57 + (j - 15)] = v;
}

// ---------------- launch ----------------
extern "C" void kernel_launch(void* const* d_in, const int* in_sizes, int n_in,
                              void* d_out, int out_size) {
    const float* x  = (const float*)d_in[0];
    const int*   ei = (const int*)d_in[1];
    const float* W1 = (const float*)d_in[2];
    const float* b1 = (const float*)d_in[3];
    const float* W2 = (const float*)d_in[4];
    const float* b2 = (const float*)d_in[5];
    const float* W3 = (const float*)d_in[6];
    const float* b3 = (const float*)d_in[7];
    const float* We = (const float*)d_in[8];
    const float* be = (const float*)d_in[9];
    const float* Wh = (const float*)d_in[10];
    const float* bh = (const float*)d_in[11];
    const float* Wg = (const float*)d_in[12];
    const float* bg = (const float*)d_in[13];

    const int* srcArr = ei;
    const int* dstArr = ei + NE;

    float* out  = (float*)d_out;
    float* emb  = out;
    float* outE = out + (size_t)NN * 256;
    float* outH = outE + (size_t)NN * 7;
    float* outG = outH + (size_t)NN * 8;

    float *buf1, *buf2;
    __half *Ah, *Bt1, *Bt2, *Bt3, *Whd;
    cudaGetSymbolAddress((void**)&buf1, g_buf1);
    cudaGetSymbolAddress((void**)&buf2, g_buf2);
    cudaGetSymbolAddress((void**)&Ah,  g_Ah);
    cudaGetSymbolAddress((void**)&Bt1, g_Bt1);
    cudaGetSymbolAddress((void**)&Bt2, g_Bt2);
    cudaGetSymbolAddress((void**)&Bt3, g_Bt3);
    cudaGetSymbolAddress((void**)&Whd, g_Whd);

    const int GEMM_SMEM = 8 * STG_BYTES;  // 81920 B
    cudaFuncSetAttribute(gemm_mma_kernel<512, 1, __half>, cudaFuncAttributeMaxDynamicSharedMemorySize, GEMM_SMEM);
    cudaFuncSetAttribute(gemm_mma_kernel<256, 2, float>,  cudaFuncAttributeMaxDynamicSharedMemorySize, GEMM_SMEM);

    // side stream + fork/join events. Created exactly once, during the eager
    // correctness call (never inside capture). Host-side objects only.
    static cudaStream_t s2 = nullptr;
    static cudaEvent_t evFork = nullptr, evJoin = nullptr;
    if (s2 == nullptr) {
        cudaStreamCreateWithFlags(&s2, cudaStreamNonBlocking);
        cudaEventCreateWithFlags(&evFork, cudaEventDisableTiming);
        cudaEventCreateWithFlags(&evJoin, cudaEventDisableTiming);
    }

    const int gm = MPAD / 128;  // 391
    __half* bufh = (__half*)buf1;
    __half* Ahd = (__half*)buf2;

    // ---- fork: branch B (s2) does CSR build + layer-2/3/head weight prep ----
    cudaEventRecord(evFork, 0);
    cudaStreamWaitEvent(s2, evFork, 0);

    convert_B_kernel<<<(512 * 512 + 255) / 256, 256, 0, s2>>>(W2, Bt2, 512);
    convert_B_kernel<<<(512 * 256 + 255) / 256, 256, 0, s2>>>(W3, Bt3, 256);
    pack_heads_kernel<<<(128 * 256 + 255) / 256, 256, 0, s2>>>(We, be, Wh, bh, Wg, bg);
    zero_indeg_kernel<<<(NN + 255) / 256, 256, 0, s2>>>();
    count_kernel<<<(NE + 255) / 256, 256, 0, s2>>>(dstArr);
    scan_part1<<<49, 1024, 0, s2>>>();
    scan_part2<<<1, 1, 0, s2>>>();
    scan_part3<<<49, 1024, 0, s2>>>();
    scatter_kernel<<<(NE + 255) / 256, 256, 0, s2>>>(srcArr, dstArr);

    // ---- main branch: x conversion + layer-1 weights + layer-1 GEMM ----
    convert_x_kernel<<<(MPAD * 128 + 255) / 256, 256>>>(x);
    convert_B_kernel<<<(512 * 512 + 255) / 256, 256>>>(W1, Bt1, 512);
    gemm_mma_kernel<512, 1, __half><<<dim3(4, gm), 256, GEMM_SMEM>>>(Ah, Bt1, bufh, NN, 512);

    // ---- join: aggregates need CSR (branch B) + GEMM output (main) ----
    cudaEventRecord(evJoin, s2);
    cudaStreamWaitEvent(0, evJoin, 0);

    aggregate_h_kernel<<<NN / 4, 256>>>(bufh, b1);   // -> g_Ah (fp16)
    // layer 2
    gemm_mma_kernel<512, 1, __half><<<dim3(4, gm), 256, GEMM_SMEM>>>(Ah, Bt2, bufh, NN, 512);
    aggregate_h_kernel<<<NN / 4, 256>>>(bufh, b2);   // -> g_Ah (fp16)
    // layer 3 (fp16 Y, emb f32 output + heads fp16 A)
    gemm_mma_kernel<512, 1, __half><<<dim3(2, gm), 256, GEMM_SMEM>>>(Ah, Bt3, bufh, NN, 256);
    aggregate3_kernel<<<MPAD / 8, 256>>>(bufh, emb, b3, Ahd);
    // heads: [NN,256] fp16 @ Whd[128, 512 split] -> buf1 f32 [NN,128]
    gemm_mma_kernel<256, 2, float><<<dim3(1, gm), 256, GEMM_SMEM>>>(Ahd, Whd, buf1, NN, 128);
    split_heads_kernel<<<(NN * 72 + 255) / 256, 256>>>(buf1, outE, outH, outG);
}